// round 13
// baseline (speedup 1.0000x reference)
#include <cuda_runtime.h>
#include <cuda_bf16.h>
#include <math.h>
#include <stdint.h>

#define T 2048
#define D 2048
#define H 16
#define HD 128
#define RD 64
#define KC 4

// ---------------- scratch (device globals) -----------------------------------
__device__ float g_q[T * D];
__device__ float g_k[T * D];
__device__ float g_v[T * D];

__device__ __nv_bfloat16 g_xh[T * D], g_xl[T * D];
__device__ __nv_bfloat16 g_wh[4][D * D], g_wl[4][D * D];  // Wq,Wk,Wv,Wo
__device__ __nv_bfloat16 g_ah[T * D], g_al[T * D];        // attn out hi/lo

// flash inputs, bf16 hi/lo, [H][T][HD]
__device__ __nv_bfloat16 g_q2h[T * D], g_q2l[T * D];
__device__ __nv_bfloat16 g_k2h[T * D], g_k2l[T * D];
__device__ __nv_bfloat16 g_v2h[T * D], g_v2l[T * D];

// ---------------- PTX helpers --------------------------------------------------
__device__ __forceinline__ uint32_t smem_u32(const void* p) {
    uint32_t a;
    asm("{ .reg .u64 t; cvta.to.shared.u64 t, %1; cvt.u32.u64 %0, t; }" : "=r"(a) : "l"(p));
    return a;
}

#define CP16(dst, src) \
    asm volatile("cp.async.cg.shared.global [%0], [%1], 16;" :: "r"(dst), "l"(src))
#define CP_COMMIT() asm volatile("cp.async.commit_group;" ::: "memory")
#define CP_WAIT(n)  asm volatile("cp.async.wait_group %0;" :: "n"(n) : "memory")

#define LDSM4(r0, r1, r2, r3, addr)                                      \
    asm volatile("ldmatrix.sync.aligned.m8n8.x4.shared.b16 {%0,%1,%2,%3}, [%4];" \
        : "=r"(r0), "=r"(r1), "=r"(r2), "=r"(r3) : "r"(addr))

#define LDSM4T(r0, r1, r2, r3, addr)                                     \
    asm volatile("ldmatrix.sync.aligned.m8n8.x4.trans.shared.b16 {%0,%1,%2,%3}, [%4];" \
        : "=r"(r0), "=r"(r1), "=r"(r2), "=r"(r3) : "r"(addr))

#define MMA16816(d, a, b)                                                \
    asm volatile("mma.sync.aligned.m16n8k16.row.col.f32.bf16.bf16.f32 "  \
        "{%0,%1,%2,%3}, {%4,%5,%6,%7}, {%8,%9}, {%0,%1,%2,%3};"          \
        : "+f"((d)[0]), "+f"((d)[1]), "+f"((d)[2]), "+f"((d)[3])         \
        : "r"((a)[0]), "r"((a)[1]), "r"((a)[2]), "r"((a)[3]),            \
          "r"((b)[0]), "r"((b)[1]))

__device__ __forceinline__ void split2(float a, float b, uint32_t& hi, uint32_t& lo) {
    __nv_bfloat162 h = __floats2bfloat162_rn(a, b);
    __nv_bfloat162 l = __floats2bfloat162_rn(a - __low2float(h), b - __high2float(h));
    hi = *(uint32_t*)&h;
    lo = *(uint32_t*)&l;
}

// ---------------- fp32 -> bf16 hi/lo split (inputs) ----------------------------
__global__ void split_bf16(const float* __restrict__ s0, __nv_bfloat16* h0, __nv_bfloat16* l0,
                           const float* __restrict__ s1, __nv_bfloat16* h1, __nv_bfloat16* l1,
                           const float* __restrict__ s2, __nv_bfloat16* h2, __nv_bfloat16* l2,
                           const float* __restrict__ s3, __nv_bfloat16* h3, __nv_bfloat16* l3,
                           const float* __restrict__ s4, __nv_bfloat16* h4, __nv_bfloat16* l4)
{
    const float* s; __nv_bfloat16 *h, *l;
    switch (blockIdx.z) {
        case 0:  s = s0; h = h0; l = l0; break;
        case 1:  s = s1; h = h1; l = l1; break;
        case 2:  s = s2; h = h2; l = l2; break;
        case 3:  s = s3; h = h3; l = l3; break;
        default: s = s4; h = h4; l = l4; break;
    }
    const int n4 = T * D / 4;
    for (int i = blockIdx.x * blockDim.x + threadIdx.x; i < n4; i += gridDim.x * blockDim.x) {
        float4 v = ((const float4*)s)[i];
        __nv_bfloat162 h01 = __floats2bfloat162_rn(v.x, v.y);
        __nv_bfloat162 h23 = __floats2bfloat162_rn(v.z, v.w);
        __nv_bfloat162 l01 = __floats2bfloat162_rn(v.x - __low2float(h01), v.y - __high2float(h01));
        __nv_bfloat162 l23 = __floats2bfloat162_rn(v.z - __low2float(h23), v.w - __high2float(h23));
        ((__nv_bfloat162*)h)[2 * i]     = h01;
        ((__nv_bfloat162*)h)[2 * i + 1] = h23;
        ((__nv_bfloat162*)l)[2 * i]     = l01;
        ((__nv_bfloat162*)l)[2 * i + 1] = l23;
    }
}

// ---------------- bf16-split GEMM (NT), 256x128, hoisted prefetch -------------
#define BK      32
#define NCK     (D / BK)
#define TILE_AB (256 * 64)
#define TILE_BB (128 * 64)
#define STAGE_B (2 * TILE_AB + 2 * TILE_BB)
#define GEMM_SMEM (3 * STAGE_B)
#define SWZ16(row, ch) ((((ch) ^ (((row) >> 1) & 3))) * 16)

__global__ __launch_bounds__(256, 1)
void gemm_bf16s(const __nv_bfloat16* __restrict__ Ah_, const __nv_bfloat16* __restrict__ Al_,
                const __nv_bfloat16* __restrict__ Bh0, const __nv_bfloat16* __restrict__ Bl0,
                const __nv_bfloat16* __restrict__ Bh1, const __nv_bfloat16* __restrict__ Bl1,
                const __nv_bfloat16* __restrict__ Bh2, const __nv_bfloat16* __restrict__ Bl2,
                float* __restrict__ C0, float* __restrict__ C1, float* __restrict__ C2)
{
    const __nv_bfloat16* Bh_ = (blockIdx.z == 0) ? Bh0 : ((blockIdx.z == 1) ? Bh1 : Bh2);
    const __nv_bfloat16* Bl_ = (blockIdx.z == 0) ? Bl0 : ((blockIdx.z == 1) ? Bl1 : Bl2);
    float*               C   = (blockIdx.z == 0) ? C0  : ((blockIdx.z == 1) ? C1  : C2);

    extern __shared__ __nv_bfloat16 sm[];
    const uint32_t sbase = smem_u32(sm);

    const int tid  = threadIdx.x;
    const int lane = tid & 31;
    const int warp = tid >> 5;
    const int wm0  = (warp & 3) * 64;
    const int wn0  = (warp >> 2) * 64;
    const int brow = blockIdx.y * 256;
    const int bcol = blockIdx.x * 128;

    auto load_chunk = [&](int c, int slot) {
        const int k0 = c * BK;
        const uint32_t s0 = sbase + (uint32_t)slot * STAGE_B;
#pragma unroll
        for (int t = 0; t < 4; t++) {
            const int idx = t * 256 + tid;
            const int r   = idx >> 2;
            const int ch  = idx & 3;
            const uint32_t so = s0 + r * 64 + SWZ16(r, ch);
            const size_t ga = (size_t)(brow + r) * D + k0 + ch * 8;
            CP16(so,           Ah_ + ga);
            CP16(so + TILE_AB, Al_ + ga);
        }
#pragma unroll
        for (int t = 0; t < 2; t++) {
            const int idx = t * 256 + tid;
            const int r   = idx >> 2;
            const int ch  = idx & 3;
            const uint32_t so = s0 + 2 * TILE_AB + r * 64 + SWZ16(r, ch);
            const size_t gb = (size_t)(bcol + r) * D + k0 + ch * 8;
            CP16(so,           Bh_ + gb);
            CP16(so + TILE_BB, Bl_ + gb);
        }
    };

    float acc[4][8][4];
#pragma unroll
    for (int mt = 0; mt < 4; mt++)
#pragma unroll
        for (int nt = 0; nt < 8; nt++)
#pragma unroll
            for (int i = 0; i < 4; i++) acc[mt][nt][i] = 0.f;

    load_chunk(0, 0); CP_COMMIT();
    load_chunk(1, 1); CP_COMMIT();

    const int arow = wm0 + (lane & 15);
    const int achk = lane >> 4;
    const int nrow = wn0 + (lane & 7) + ((lane & 16) >> 1);
    const int bchk = (lane & 8) >> 3;

    for (int c = 0; c < NCK; c++) {
        CP_WAIT(1);
        __syncthreads();
        // hoisted prefetch: slot (c+2)%3 == slot (c-1)%3, free after the sync
        if (c + 2 < NCK) load_chunk(c + 2, (c + 2) % 3);
        CP_COMMIT();

        const uint32_t sbm = sbase + (uint32_t)(c % 3) * STAGE_B;
#pragma unroll
        for (int ks = 0; ks < 2; ks++) {
            uint32_t ah[4][4], al[4][4], bh[8][2], bl[8][2];
#pragma unroll
            for (int mt = 0; mt < 4; mt++) {
                const int lrow = arow + mt * 16;
                const uint32_t ad = sbm + lrow * 64 + SWZ16(lrow, ks * 2 + achk);
                LDSM4(ah[mt][0], ah[mt][1], ah[mt][2], ah[mt][3], ad);
                LDSM4(al[mt][0], al[mt][1], al[mt][2], al[mt][3], ad + TILE_AB);
            }
#pragma unroll
            for (int np = 0; np < 4; np++) {
                const int brw = nrow + np * 16;
                const uint32_t bd = sbm + 2 * TILE_AB + brw * 64 + SWZ16(brw, ks * 2 + bchk);
                LDSM4(bh[2 * np][0], bh[2 * np][1], bh[2 * np + 1][0], bh[2 * np + 1][1], bd);
                LDSM4(bl[2 * np][0], bl[2 * np][1], bl[2 * np + 1][0], bl[2 * np + 1][1],
                      bd + TILE_BB);
            }
#pragma unroll
            for (int mt = 0; mt < 4; mt++)
#pragma unroll
                for (int nt = 0; nt < 8; nt++) MMA16816(acc[mt][nt], ah[mt], bh[nt]);
#pragma unroll
            for (int mt = 0; mt < 4; mt++)
#pragma unroll
                for (int nt = 0; nt < 8; nt++) MMA16816(acc[mt][nt], ah[mt], bl[nt]);
#pragma unroll
            for (int mt = 0; mt < 4; mt++)
#pragma unroll
                for (int nt = 0; nt < 8; nt++) MMA16816(acc[mt][nt], al[mt], bh[nt]);
        }
    }

#pragma unroll
    for (int mt = 0; mt < 4; mt++) {
        const int row = brow + wm0 + mt * 16 + (lane >> 2);
#pragma unroll
        for (int nt = 0; nt < 8; nt++) {
            const int col = bcol + wn0 + nt * 8 + 2 * (lane & 3);
            float* p = C + (size_t)row * D + col;
            p[0] = acc[mt][nt][0];
            p[1] = acc[mt][nt][1];
            p += 8 * (size_t)D;
            p[0] = acc[mt][nt][2];
            p[1] = acc[mt][nt][3];
        }
    }
}

// -------- fused post v2: 4 t-values per block ---------------------------------
__global__ void fuse_post(const float* __restrict__ cosb,
                          const float* __restrict__ sinb,
                          const float* __restrict__ wq,
                          const float* __restrict__ wk,
                          const float* __restrict__ wv,
                          const float* __restrict__ qnw,
                          const float* __restrict__ knw)
{
    const int t0 = blockIdx.x * 4;
    const int h  = blockIdx.y;
    const int hd = threadIdx.x;
    const int d  = h * HD + hd;

    float xq[7], xk[7], xv[7];
#pragma unroll
    for (int i = 0; i < 7; i++) {
        const int tt = t0 - 3 + i;
        if (tt >= 0) {
            const size_t o = (size_t)tt * D + d;
            xq[i] = g_q[o]; xk[i] = g_k[o]; xv[i] = g_v[o];
        } else {
            xq[i] = 0.f; xk[i] = 0.f; xv[i] = 0.f;
        }
    }
    float wqr[4], wkr[4], wvr[4];
#pragma unroll
    for (int j = 0; j < 4; j++) {
        wqr[j] = wq[d * KC + j]; wkr[j] = wk[d * KC + j]; wvr[j] = wv[d * KC + j];
    }

    float yq[4], yk[4], yv[4];
#pragma unroll
    for (int ti = 0; ti < 4; ti++) {
        float aq = 0.f, ak = 0.f, av = 0.f;
#pragma unroll
        for (int j = 0; j < 4; j++) {
            aq = fmaf(xq[ti + j], wqr[j], aq);
            ak = fmaf(xk[ti + j], wkr[j], ak);
            av = fmaf(xv[ti + j], wvr[j], av);
        }
        yq[ti] = aq / (1.f + __expf(-aq));
        yk[ti] = ak / (1.f + __expf(-ak));
        yv[ti] = av / (1.f + __expf(-av));
    }

    __shared__ float rq[4][4], rk[4][4], sq[4][HD], sk[4][HD];
    const int w = hd >> 5;
    float vq[4], vk[4];
#pragma unroll
    for (int ti = 0; ti < 4; ti++) { vq[ti] = yq[ti] * yq[ti]; vk[ti] = yk[ti] * yk[ti]; }
#pragma unroll
    for (int off = 16; off > 0; off >>= 1) {
#pragma unroll
        for (int ti = 0; ti < 4; ti++) {
            vq[ti] += __shfl_xor_sync(0xffffffffu, vq[ti], off);
            vk[ti] += __shfl_xor_sync(0xffffffffu, vk[ti], off);
        }
    }
    if ((hd & 31) == 0) {
#pragma unroll
        for (int ti = 0; ti < 4; ti++) { rq[ti][w] = vq[ti]; rk[ti][w] = vk[ti]; }
    }
    __syncthreads();
#pragma unroll
    for (int ti = 0; ti < 4; ti++) {
        const float varq = (rq[ti][0] + rq[ti][1] + rq[ti][2] + rq[ti][3]) * (1.f / HD);
        const float vark = (rk[ti][0] + rk[ti][1] + rk[ti][2] + rk[ti][3]) * (1.f / HD);
        sq[ti][hd] = yq[ti] * rsqrtf(varq + 1e-5f) * qnw[hd];
        sk[ti][hd] = yk[ti] * rsqrtf(vark + 1e-5f) * knw[hd];
    }
    __syncthreads();

    const float scale = 0.08838834764831845f * 1.4426950408889634f;

#pragma unroll
    for (int ti = 0; ti < 4; ti++) {
        const int t = t0 + ti;
        float oq, ok;
        if (hd < RD) {
            const float cs = cosb[t * RD + hd];
            const float sn = sinb[t * RD + hd];
            const float rqv = (hd < RD / 2) ? -sq[ti][hd + RD / 2] : sq[ti][hd - RD / 2];
            const float rkv = (hd < RD / 2) ? -sk[ti][hd + RD / 2] : sk[ti][hd - RD / 2];
            oq = -(sq[ti][hd] * cs + rqv * sn);
            ok = -(sk[ti][hd] * cs + rkv * sn);
        } else {
            oq = sq[ti][hd];
            ok = sk[ti][hd];
        }
        oq *= scale;

        const size_t o = ((size_t)h * T + t) * HD + hd;
        __nv_bfloat16 b;
        b = __float2bfloat16(oq);
        g_q2h[o] = b; g_q2l[o] = __float2bfloat16(oq - __bfloat162float(b));
        b = __float2bfloat16(ok);
        g_k2h[o] = b; g_k2l[o] = __float2bfloat16(ok - __bfloat162float(b));
        b = __float2bfloat16(yv[ti]);
        g_v2h[o] = b; g_v2l[o] = __float2bfloat16(yv[ti] - __bfloat162float(b));
    }
}

// ---------------- flash attention (best-known form, frozen) -------------------
#define FSTR   136
#define FQT    (64 * FSTR)
#define FKT    (32 * FSTR)
#define FSMEM  ((2 * FQT + 8 * FKT) * 2)  // 104448 B -> 2 CTAs/SM

__global__ __launch_bounds__(128, 2)
void flash_mma()
{
    extern __shared__ __nv_bfloat16 fsm[];

    const int tid  = threadIdx.x;
    const int lane = tid & 31;
    const int wm   = tid >> 5;
    const int h    = blockIdx.y;
    const int qt   = gridDim.x - 1 - blockIdx.x;
    const int q0   = qt * 64;

    const uint32_t sb = smem_u32(fsm);

    auto ldq = [&]() {
#pragma unroll
        for (int t = 0; t < 8; t++) {
            const int idx = t * 128 + tid;
            const int r   = idx >> 4;
            const int cc  = idx & 15;
            const uint32_t so = 2 * (r * FSTR + cc * 8);
            const size_t  go = ((size_t)h * T + q0 + r) * HD + cc * 8;
            CP16(sb + so,           g_q2h + go);
            CP16(sb + 2 * FQT + so, g_q2l + go);
        }
    };
    auto ldkv = [&](int kt2, int s) {
        const uint32_t kb = sb + 2 * (2 * FQT + (uint32_t)s * 4 * FKT);
#pragma unroll
        for (int t = 0; t < 4; t++) {
            const int idx = t * 128 + tid;
            const int r   = idx >> 4;
            const int cc  = idx & 15;
            const uint32_t so = 2 * (r * FSTR + cc * 8);
            const size_t  go = ((size_t)h * T + kt2 * 32 + r) * HD + cc * 8;
            CP16(kb + so,           g_k2h + go);
            CP16(kb + 2 * FKT + so, g_k2l + go);
            CP16(kb + 4 * FKT + so, g_v2h + go);
            CP16(kb + 6 * FKT + so, g_v2l + go);
        }
    };

    float acco[16][4];
#pragma unroll
    for (int nt = 0; nt < 16; nt++)
#pragma unroll
        for (int i = 0; i < 4; i++) acco[nt][i] = 0.f;
    float m0 = -1e30f, m1 = -1e30f, l0 = 0.f, l1 = 0.f;

    ldq(); ldkv(0, 0); CP_COMMIT();
    ldkv(1, 1); CP_COMMIT();

    const int r0l = wm * 16 + (lane >> 2);
    const int r1l = r0l + 8;
    const uint32_t qoff = 2 * ((wm * 16 + (lane & 15)) * FSTR + ((lane >> 4) << 3));
    const int krow = (lane & 7) + ((lane & 16) >> 1);
    const int rowMax = q0 + wm * 16 + 15;

    CP_WAIT(1);
    __syncthreads();
    uint32_t qh[8][4], ql[8][4];
#pragma unroll
    for (int j = 0; j < 8; j++) {
        const uint32_t qa = sb + qoff + 2 * (j * 16);
        LDSM4(qh[j][0], qh[j][1], qh[j][2], qh[j][3], qa);
        LDSM4(ql[j][0], ql[j][1], ql[j][2], ql[j][3], qa + 2 * FQT);
    }

    const int NKV = 2 * qt + 2;

    for (int kt = 0; kt < NKV; kt++) {
        if (kt > 0) {
            CP_WAIT(1);
            __syncthreads();
        }

        const bool active = (kt * 32 <= rowMax);
        const uint32_t kb = sb + 2 * (2 * FQT + (uint32_t)(kt & 1) * 4 * FKT);

        if (active) {
            float accA[4][4], accB[4][4];
#pragma unroll
            for (int nt = 0; nt < 4; nt++)
#pragma unroll
                for (int i = 0; i < 4; i++) { accA[nt][i] = 0.f; accB[nt][i] = 0.f; }

#pragma unroll
            for (int j = 0; j < 8; j++) {
                uint32_t bh[4][2], bl[4][2];
#pragma unroll
                for (int np = 0; np < 2; np++) {
                    const uint32_t ka = kb + 2 * ((np * 16 + krow) * FSTR + j * 16 + (lane & 8));
                    LDSM4(bh[2 * np][0], bh[2 * np][1], bh[2 * np + 1][0], bh[2 * np + 1][1], ka);
                    LDSM4(bl[2 * np][0], bl[2 * np][1], bl[2 * np + 1][0], bl[2 * np + 1][1],
                          ka + 2 * FKT);
                }
#pragma unroll
                for (int nt = 0; nt < 4; nt++) MMA16816(accA[nt], qh[j], bh[nt]);
#pragma unroll
                for (int nt = 0; nt < 4; nt++) MMA16816(accB[nt], qh[j], bl[nt]);
#pragma unroll
                for (int nt = 0; nt < 4; nt++) MMA16816(accB[nt], ql[j], bh[nt]);
            }

            float accs[4][4];
#pragma unroll
            for (int nt = 0; nt < 4; nt++)
#pragma unroll
                for (int i = 0; i < 4; i++) accs[nt][i] = accA[nt][i] + accB[nt][i];

            if (kt >= 2 * qt) {
                const int gr0 = q0 + r0l, gr1 = q0 + r1l;
#pragma unroll
                for (int nt = 0; nt < 4; nt++) {
                    const int c0 = kt * 32 + nt * 8 + 2 * (lane & 3);
                    if (c0     > gr0) accs[nt][0] = -1e30f;
                    if (c0 + 1 > gr0) accs[nt][1] = -1e30f;
                    if (c0     > gr1) accs[nt][2] = -1e30f;
                    if (c0 + 1 > gr1) accs[nt][3] = -1e30f;
                }
            }

            float mx0 = -1e30f, mx1 = -1e30f;
#pragma unroll
            for (int nt = 0; nt < 4; nt++) {
                mx0 = fmaxf(mx0, fmaxf(accs[nt][0], accs[nt][1]));
                mx1 = fmaxf(mx1, fmaxf(accs[nt][2], accs[nt][3]));
            }
            mx0 = fmaxf(mx0, __shfl_xor_sync(0xffffffffu, mx0, 1));
            mx0 = fmaxf(mx0, __shfl_xor_sync(0xffffffffu, mx0, 2));
            mx1 = fmaxf(mx1, __shfl_xor_sync(0xffffffffu, mx1, 1));
            mx1 = fmaxf(mx1, __shfl_xor_sync(0xffffffffu, mx1, 2));
            const float mn0 = fmaxf(m0, mx0), mn1 = fmaxf(m1, mx1);
            const float c0 = exp2f(m0 - mn0), c1 = exp2f(m1 - mn1);

            float p[4][4];
            float ps0 = 0.f, ps1 = 0.f;
#pragma unroll
            for (int nt = 0; nt < 4; nt++) {
                p[nt][0] = exp2f(accs[nt][0] - mn0); ps0 += p[nt][0];
                p[nt][1] = exp2f(accs[nt][1] - mn0); ps0 += p[nt][1];
                p[nt][2] = exp2f(accs[nt][2] - mn1); ps1 += p[nt][2];
                p[nt][3] = exp2f(accs[nt][3] - mn1); ps1 += p[nt][3];
            }
            ps0 += __shfl_xor_sync(0xffffffffu, ps0, 1);
            ps0 += __shfl_xor_sync(0xffffffffu, ps0, 2);
            ps1 += __shfl_xor_sync(0xffffffffu, ps1, 1);
            ps1 += __shfl_xor_sync(0xffffffffu, ps1, 2);
            l0 = l0 * c0 + ps0;
            l1 = l1 * c1 + ps1;
            m0 = mn0; m1 = mn1;

#pragma unroll
            for (int nt = 0; nt < 16; nt++) {
                acco[nt][0] *= c0; acco[nt][1] *= c0;
                acco[nt][2] *= c1; acco[nt][3] *= c1;
            }

            uint32_t pha[2][4], pla[2][4];
#pragma unroll
            for (int j = 0; j < 2; j++) {
                split2(p[2 * j][0],     p[2 * j][1],     pha[j][0], pla[j][0]);
                split2(p[2 * j][2],     p[2 * j][3],     pha[j][1], pla[j][1]);
                split2(p[2 * j + 1][0], p[2 * j + 1][1], pha[j][2], pla[j][2]);
                split2(p[2 * j + 1][2], p[2 * j + 1][3], pha[j][3], pla[j][3]);
            }

            const uint32_t vb = kb + 4 * FKT;
#pragma unroll
            for (int j = 0; j < 2; j++) {
                const int k0 = j * 16 + (lane & 15);
#pragma unroll
                for (int np = 0; np < 8; np++) {
                    const uint32_t va = vb + 2 * (k0 * FSTR + np * 16 + ((lane >> 4) << 3));
                    uint32_t vh[4], vl[4];
                    LDSM4T(vh[0], vh[1], vh[2], vh[3], va);
                    LDSM4T(vl[0], vl[1], vl[2], vl[3], va + 2 * FKT);
                    MMA16816(acco[2 * np],     pha[j], vh);
                    MMA16816(acco[2 * np + 1], pha[j], vh + 2);
                    MMA16816(acco[2 * np],     pha[j], vl);
                    MMA16816(acco[2 * np + 1], pha[j], vl + 2);
                    MMA16816(acco[2 * np],     pla[j], vh);
                    MMA16816(acco[2 * np + 1], pla[j], vh + 2);
                }
            }
        }

        __syncthreads();
        if (kt + 2 < NKV) ldkv(kt + 2, kt & 1);
        CP_COMMIT();
    }

    const float il0 = 1.f / l0, il1 = 1.f / l1;
#pragma unroll
    for (int nt = 0; nt < 16; nt++) {
        const int col = nt * 8 + 2 * (lane & 3);
        const float v0 = acco[nt][0] * il0;
        const float v1 = acco[nt][1] * il0;
        const float v2 = acco[nt][2] * il1;
        const float v3 = acco[nt][3] * il1;
        uint32_t hi, lo;
        const size_t o0 = (size_t)(q0 + r0l) * D + h * HD + col;
        const size_t o1 = (size_t)(q0 + r1l) * D + h * HD + col;
        split2(v0, v1, hi, lo);
        *(uint32_t*)&g_ah[o0] = hi; *(uint32_t*)&g_al[o0] = lo;
        split2(v2, v3, hi, lo);
        *(uint32_t*)&g_ah[o1] = hi; *(uint32_t*)&g_al[o1] = lo;
    }
}

// -----------------------------------------------------------------------------
extern "C" void kernel_launch(void* const* d_in, const int* in_sizes, int n_in,
                              void* d_out, int out_size)
{
    const float* x    = (const float*)d_in[0];
    const float* cosb = (const float*)d_in[1];
    const float* sinb = (const float*)d_in[2];
    const float* Wq   = (const float*)d_in[3];
    const float* Wk   = (const float*)d_in[4];
    const float* Wv   = (const float*)d_in[5];
    const float* Wo   = (const float*)d_in[6];
    const float* wq   = (const float*)d_in[7];
    const float* wk   = (const float*)d_in[8];
    const float* wv   = (const float*)d_in[9];
    const float* qnw  = (const float*)d_in[10];
    const float* knw  = (const float*)d_in[11];
    float* out = (float*)d_out;

    float *pq, *pk, *pv;
    __nv_bfloat16 *pxh, *pxl, *pwh, *pwl, *pah, *pal;
    cudaGetSymbolAddress((void**)&pq, g_q);
    cudaGetSymbolAddress((void**)&pk, g_k);
    cudaGetSymbolAddress((void**)&pv, g_v);
    cudaGetSymbolAddress((void**)&pxh, g_xh);
    cudaGetSymbolAddress((void**)&pxl, g_xl);
    cudaGetSymbolAddress((void**)&pwh, g_wh);
    cudaGetSymbolAddress((void**)&pwl, g_wl);
    cudaGetSymbolAddress((void**)&pah, g_ah);
    cudaGetSymbolAddress((void**)&pal, g_al);

    __nv_bfloat16* wh[4];
    __nv_bfloat16* wl[4];
    for (int i = 0; i < 4; i++) { wh[i] = pwh + (size_t)i * D * D; wl[i] = pwl + (size_t)i * D * D; }

    cudaFuncSetAttribute(gemm_bf16s, cudaFuncAttributeMaxDynamicSharedMemorySize, GEMM_SMEM);
    cudaFuncSetAttribute(flash_mma,  cudaFuncAttributeMaxDynamicSharedMemorySize, FSMEM);

    // 0) split x, Wq, Wk, Wv, Wo into bf16 hi/lo
    split_bf16<<<dim3(256, 1, 5), 256>>>(x, pxh, pxl,
                                         Wq, wh[0], wl[0],
                                         Wk, wh[1], wl[1],
                                         Wv, wh[2], wl[2],
                                         Wo, wh[3], wl[3]);

    // 1) QKV projections (256x128 tiles, hoisted prefetch)
    gemm_bf16s<<<dim3(D / 128, T / 256, 3), 256, GEMM_SMEM>>>(pxh, pxl,
                                                    wh[0], wl[0], wh[1], wl[1], wh[2], wl[2],
                                                    pq, pk, pv);

    // 2) conv + SiLU + RMSNorm + RoPE + transpose (4 t per block)
    fuse_post<<<dim3(T / 4, H), HD>>>(cosb, sinb, wq, wk, wv, qnw, knw);

    // 3) causal flash attention
    flash_mma<<<dim3(T / 64, H), 128, FSMEM>>>();

    // 4) O-proj -> d_out
    gemm_bf16s<<<dim3(D / 128, T / 256, 1), 256, GEMM_SMEM>>>(pah, pal,
                                                    wh[3], wl[3], wh[3], wl[3], wh[3], wl[3],
                                                    out, out, out);
}

// round 14
// speedup vs baseline: 1.0516x; 1.0516x over previous
#include <cuda_runtime.h>
#include <cuda_bf16.h>
#include <math.h>
#include <stdint.h>

#define T 2048
#define D 2048
#define H 16
#define HD 128
#define RD 64
#define KC 4

// ---------------- scratch (device globals) -----------------------------------
__device__ float g_q[T * D];
__device__ float g_k[T * D];
__device__ float g_v[T * D];

__device__ __nv_bfloat16 g_xh[T * D], g_xl[T * D];
__device__ __nv_bfloat16 g_wh[4][D * D], g_wl[4][D * D];  // Wq,Wk,Wv,Wo
__device__ __nv_bfloat16 g_ah[T * D], g_al[T * D];        // attn out hi/lo

// flash inputs, bf16 hi/lo, [H][T][HD]
__device__ __nv_bfloat16 g_q2h[T * D], g_q2l[T * D];
__device__ __nv_bfloat16 g_k2h[T * D], g_k2l[T * D];
__device__ __nv_bfloat16 g_v2h[T * D], g_v2l[T * D];

// ---------------- PTX helpers --------------------------------------------------
__device__ __forceinline__ uint32_t smem_u32(const void* p) {
    uint32_t a;
    asm("{ .reg .u64 t; cvta.to.shared.u64 t, %1; cvt.u32.u64 %0, t; }" : "=r"(a) : "l"(p));
    return a;
}

#define CP16(dst, src) \
    asm volatile("cp.async.cg.shared.global [%0], [%1], 16;" :: "r"(dst), "l"(src))
#define CP_COMMIT() asm volatile("cp.async.commit_group;" ::: "memory")
#define CP_WAIT(n)  asm volatile("cp.async.wait_group %0;" :: "n"(n) : "memory")

#define LDSM4(r0, r1, r2, r3, addr)                                      \
    asm volatile("ldmatrix.sync.aligned.m8n8.x4.shared.b16 {%0,%1,%2,%3}, [%4];" \
        : "=r"(r0), "=r"(r1), "=r"(r2), "=r"(r3) : "r"(addr))

#define LDSM4T(r0, r1, r2, r3, addr)                                     \
    asm volatile("ldmatrix.sync.aligned.m8n8.x4.trans.shared.b16 {%0,%1,%2,%3}, [%4];" \
        : "=r"(r0), "=r"(r1), "=r"(r2), "=r"(r3) : "r"(addr))

#define MMA16816(d, a, b)                                                \
    asm volatile("mma.sync.aligned.m16n8k16.row.col.f32.bf16.bf16.f32 "  \
        "{%0,%1,%2,%3}, {%4,%5,%6,%7}, {%8,%9}, {%0,%1,%2,%3};"          \
        : "+f"((d)[0]), "+f"((d)[1]), "+f"((d)[2]), "+f"((d)[3])         \
        : "r"((a)[0]), "r"((a)[1]), "r"((a)[2]), "r"((a)[3]),            \
          "r"((b)[0]), "r"((b)[1]))

__device__ __forceinline__ void split2(float a, float b, uint32_t& hi, uint32_t& lo) {
    __nv_bfloat162 h = __floats2bfloat162_rn(a, b);
    __nv_bfloat162 l = __floats2bfloat162_rn(a - __low2float(h), b - __high2float(h));
    hi = *(uint32_t*)&h;
    lo = *(uint32_t*)&l;
}

// ---------------- fp32 -> bf16 hi/lo split (inputs) ----------------------------
__global__ void split_bf16(const float* __restrict__ s0, __nv_bfloat16* h0, __nv_bfloat16* l0,
                           const float* __restrict__ s1, __nv_bfloat16* h1, __nv_bfloat16* l1,
                           const float* __restrict__ s2, __nv_bfloat16* h2, __nv_bfloat16* l2,
                           const float* __restrict__ s3, __nv_bfloat16* h3, __nv_bfloat16* l3,
                           const float* __restrict__ s4, __nv_bfloat16* h4, __nv_bfloat16* l4)
{
    const float* s; __nv_bfloat16 *h, *l;
    switch (blockIdx.z) {
        case 0:  s = s0; h = h0; l = l0; break;
        case 1:  s = s1; h = h1; l = l1; break;
        case 2:  s = s2; h = h2; l = l2; break;
        case 3:  s = s3; h = h3; l = l3; break;
        default: s = s4; h = h4; l = l4; break;
    }
    const int n4 = T * D / 4;
    for (int i = blockIdx.x * blockDim.x + threadIdx.x; i < n4; i += gridDim.x * blockDim.x) {
        float4 v = ((const float4*)s)[i];
        __nv_bfloat162 h01 = __floats2bfloat162_rn(v.x, v.y);
        __nv_bfloat162 h23 = __floats2bfloat162_rn(v.z, v.w);
        __nv_bfloat162 l01 = __floats2bfloat162_rn(v.x - __low2float(h01), v.y - __high2float(h01));
        __nv_bfloat162 l23 = __floats2bfloat162_rn(v.z - __low2float(h23), v.w - __high2float(h23));
        ((__nv_bfloat162*)h)[2 * i]     = h01;
        ((__nv_bfloat162*)h)[2 * i + 1] = h23;
        ((__nv_bfloat162*)l)[2 * i]     = l01;
        ((__nv_bfloat162*)l)[2 * i + 1] = l23;
    }
}

// ---------------- bf16-split GEMM (NT), 256x128, late prefetch (R12 best) -----
#define BK      32
#define NCK     (D / BK)
#define TILE_AB (256 * 64)
#define TILE_BB (128 * 64)
#define STAGE_B (2 * TILE_AB + 2 * TILE_BB)
#define GEMM_SMEM (3 * STAGE_B)
#define SWZ16(row, ch) ((((ch) ^ (((row) >> 1) & 3))) * 16)

__global__ __launch_bounds__(256, 1)
void gemm_bf16s(const __nv_bfloat16* __restrict__ Ah_, const __nv_bfloat16* __restrict__ Al_,
                const __nv_bfloat16* __restrict__ Bh0, const __nv_bfloat16* __restrict__ Bl0,
                const __nv_bfloat16* __restrict__ Bh1, const __nv_bfloat16* __restrict__ Bl1,
                const __nv_bfloat16* __restrict__ Bh2, const __nv_bfloat16* __restrict__ Bl2,
                float* __restrict__ C0, float* __restrict__ C1, float* __restrict__ C2)
{
    const __nv_bfloat16* Bh_ = (blockIdx.z == 0) ? Bh0 : ((blockIdx.z == 1) ? Bh1 : Bh2);
    const __nv_bfloat16* Bl_ = (blockIdx.z == 0) ? Bl0 : ((blockIdx.z == 1) ? Bl1 : Bl2);
    float*               C   = (blockIdx.z == 0) ? C0  : ((blockIdx.z == 1) ? C1  : C2);

    extern __shared__ __nv_bfloat16 sm[];
    const uint32_t sbase = smem_u32(sm);

    const int tid  = threadIdx.x;
    const int lane = tid & 31;
    const int warp = tid >> 5;
    const int wm0  = (warp & 3) * 64;
    const int wn0  = (warp >> 2) * 64;
    const int brow = blockIdx.y * 256;
    const int bcol = blockIdx.x * 128;

    auto load_chunk = [&](int c, int slot) {
        const int k0 = c * BK;
        const uint32_t s0 = sbase + (uint32_t)slot * STAGE_B;
#pragma unroll
        for (int t = 0; t < 4; t++) {
            const int idx = t * 256 + tid;
            const int r   = idx >> 2;
            const int ch  = idx & 3;
            const uint32_t so = s0 + r * 64 + SWZ16(r, ch);
            const size_t ga = (size_t)(brow + r) * D + k0 + ch * 8;
            CP16(so,           Ah_ + ga);
            CP16(so + TILE_AB, Al_ + ga);
        }
#pragma unroll
        for (int t = 0; t < 2; t++) {
            const int idx = t * 256 + tid;
            const int r   = idx >> 2;
            const int ch  = idx & 3;
            const uint32_t so = s0 + 2 * TILE_AB + r * 64 + SWZ16(r, ch);
            const size_t gb = (size_t)(bcol + r) * D + k0 + ch * 8;
            CP16(so,           Bh_ + gb);
            CP16(so + TILE_BB, Bl_ + gb);
        }
    };

    float acc[4][8][4];
#pragma unroll
    for (int mt = 0; mt < 4; mt++)
#pragma unroll
        for (int nt = 0; nt < 8; nt++)
#pragma unroll
            for (int i = 0; i < 4; i++) acc[mt][nt][i] = 0.f;

    load_chunk(0, 0); CP_COMMIT();
    load_chunk(1, 1); CP_COMMIT();

    const int arow = wm0 + (lane & 15);
    const int achk = lane >> 4;
    const int nrow = wn0 + (lane & 7) + ((lane & 16) >> 1);
    const int bchk = (lane & 8) >> 3;

    for (int c = 0; c < NCK; c++) {
        CP_WAIT(1);
        __syncthreads();

        const uint32_t sbm = sbase + (uint32_t)(c % 3) * STAGE_B;
#pragma unroll
        for (int ks = 0; ks < 2; ks++) {
            uint32_t ah[4][4], al[4][4], bh[8][2], bl[8][2];
#pragma unroll
            for (int mt = 0; mt < 4; mt++) {
                const int lrow = arow + mt * 16;
                const uint32_t ad = sbm + lrow * 64 + SWZ16(lrow, ks * 2 + achk);
                LDSM4(ah[mt][0], ah[mt][1], ah[mt][2], ah[mt][3], ad);
                LDSM4(al[mt][0], al[mt][1], al[mt][2], al[mt][3], ad + TILE_AB);
            }
#pragma unroll
            for (int np = 0; np < 4; np++) {
                const int brw = nrow + np * 16;
                const uint32_t bd = sbm + 2 * TILE_AB + brw * 64 + SWZ16(brw, ks * 2 + bchk);
                LDSM4(bh[2 * np][0], bh[2 * np][1], bh[2 * np + 1][0], bh[2 * np + 1][1], bd);
                LDSM4(bl[2 * np][0], bl[2 * np][1], bl[2 * np + 1][0], bl[2 * np + 1][1],
                      bd + TILE_BB);
            }
#pragma unroll
            for (int mt = 0; mt < 4; mt++)
#pragma unroll
                for (int nt = 0; nt < 8; nt++) MMA16816(acc[mt][nt], ah[mt], bh[nt]);
#pragma unroll
            for (int mt = 0; mt < 4; mt++)
#pragma unroll
                for (int nt = 0; nt < 8; nt++) MMA16816(acc[mt][nt], ah[mt], bl[nt]);
#pragma unroll
            for (int mt = 0; mt < 4; mt++)
#pragma unroll
                for (int nt = 0; nt < 8; nt++) MMA16816(acc[mt][nt], al[mt], bh[nt]);
        }

        if (c + 2 < NCK) load_chunk(c + 2, (c + 2) % 3);
        CP_COMMIT();
    }

#pragma unroll
    for (int mt = 0; mt < 4; mt++) {
        const int row = brow + wm0 + mt * 16 + (lane >> 2);
#pragma unroll
        for (int nt = 0; nt < 8; nt++) {
            const int col = bcol + wn0 + nt * 8 + 2 * (lane & 3);
            float* p = C + (size_t)row * D + col;
            p[0] = acc[mt][nt][0];
            p[1] = acc[mt][nt][1];
            p += 8 * (size_t)D;
            p[0] = acc[mt][nt][2];
            p[1] = acc[mt][nt][3];
        }
    }
}

// -------- fused post v2: 4 t-values per block ---------------------------------
__global__ void fuse_post(const float* __restrict__ cosb,
                          const float* __restrict__ sinb,
                          const float* __restrict__ wq,
                          const float* __restrict__ wk,
                          const float* __restrict__ wv,
                          const float* __restrict__ qnw,
                          const float* __restrict__ knw)
{
    const int t0 = blockIdx.x * 4;
    const int h  = blockIdx.y;
    const int hd = threadIdx.x;
    const int d  = h * HD + hd;

    float xq[7], xk[7], xv[7];
#pragma unroll
    for (int i = 0; i < 7; i++) {
        const int tt = t0 - 3 + i;
        if (tt >= 0) {
            const size_t o = (size_t)tt * D + d;
            xq[i] = g_q[o]; xk[i] = g_k[o]; xv[i] = g_v[o];
        } else {
            xq[i] = 0.f; xk[i] = 0.f; xv[i] = 0.f;
        }
    }
    float wqr[4], wkr[4], wvr[4];
#pragma unroll
    for (int j = 0; j < 4; j++) {
        wqr[j] = wq[d * KC + j]; wkr[j] = wk[d * KC + j]; wvr[j] = wv[d * KC + j];
    }

    float yq[4], yk[4], yv[4];
#pragma unroll
    for (int ti = 0; ti < 4; ti++) {
        float aq = 0.f, ak = 0.f, av = 0.f;
#pragma unroll
        for (int j = 0; j < 4; j++) {
            aq = fmaf(xq[ti + j], wqr[j], aq);
            ak = fmaf(xk[ti + j], wkr[j], ak);
            av = fmaf(xv[ti + j], wvr[j], av);
        }
        yq[ti] = aq / (1.f + __expf(-aq));
        yk[ti] = ak / (1.f + __expf(-ak));
        yv[ti] = av / (1.f + __expf(-av));
    }

    __shared__ float rq[4][4], rk[4][4], sq[4][HD], sk[4][HD];
    const int w = hd >> 5;
    float vq[4], vk[4];
#pragma unroll
    for (int ti = 0; ti < 4; ti++) { vq[ti] = yq[ti] * yq[ti]; vk[ti] = yk[ti] * yk[ti]; }
#pragma unroll
    for (int off = 16; off > 0; off >>= 1) {
#pragma unroll
        for (int ti = 0; ti < 4; ti++) {
            vq[ti] += __shfl_xor_sync(0xffffffffu, vq[ti], off);
            vk[ti] += __shfl_xor_sync(0xffffffffu, vk[ti], off);
        }
    }
    if ((hd & 31) == 0) {
#pragma unroll
        for (int ti = 0; ti < 4; ti++) { rq[ti][w] = vq[ti]; rk[ti][w] = vk[ti]; }
    }
    __syncthreads();
#pragma unroll
    for (int ti = 0; ti < 4; ti++) {
        const float varq = (rq[ti][0] + rq[ti][1] + rq[ti][2] + rq[ti][3]) * (1.f / HD);
        const float vark = (rk[ti][0] + rk[ti][1] + rk[ti][2] + rk[ti][3]) * (1.f / HD);
        sq[ti][hd] = yq[ti] * rsqrtf(varq + 1e-5f) * qnw[hd];
        sk[ti][hd] = yk[ti] * rsqrtf(vark + 1e-5f) * knw[hd];
    }
    __syncthreads();

    const float scale = 0.08838834764831845f * 1.4426950408889634f;

#pragma unroll
    for (int ti = 0; ti < 4; ti++) {
        const int t = t0 + ti;
        float oq, ok;
        if (hd < RD) {
            const float cs = cosb[t * RD + hd];
            const float sn = sinb[t * RD + hd];
            const float rqv = (hd < RD / 2) ? -sq[ti][hd + RD / 2] : sq[ti][hd - RD / 2];
            const float rkv = (hd < RD / 2) ? -sk[ti][hd + RD / 2] : sk[ti][hd - RD / 2];
            oq = -(sq[ti][hd] * cs + rqv * sn);
            ok = -(sk[ti][hd] * cs + rkv * sn);
        } else {
            oq = sq[ti][hd];
            ok = sk[ti][hd];
        }
        oq *= scale;

        const size_t o = ((size_t)h * T + t) * HD + hd;
        __nv_bfloat16 b;
        b = __float2bfloat16(oq);
        g_q2h[o] = b; g_q2l[o] = __float2bfloat16(oq - __bfloat162float(b));
        b = __float2bfloat16(ok);
        g_k2h[o] = b; g_k2l[o] = __float2bfloat16(ok - __bfloat162float(b));
        b = __float2bfloat16(yv[ti]);
        g_v2h[o] = b; g_v2l[o] = __float2bfloat16(yv[ti] - __bfloat162float(b));
    }
}

// ---------------- flash attention (best-known form, frozen) -------------------
#define FSTR   136
#define FQT    (64 * FSTR)
#define FKT    (32 * FSTR)
#define FSMEM  ((2 * FQT + 8 * FKT) * 2)  // 104448 B -> 2 CTAs/SM

__global__ __launch_bounds__(128, 2)
void flash_mma()
{
    extern __shared__ __nv_bfloat16 fsm[];

    const int tid  = threadIdx.x;
    const int lane = tid & 31;
    const int wm   = tid >> 5;
    const int h    = blockIdx.y;
    const int qt   = gridDim.x - 1 - blockIdx.x;
    const int q0   = qt * 64;

    const uint32_t sb = smem_u32(fsm);

    auto ldq = [&]() {
#pragma unroll
        for (int t = 0; t < 8; t++) {
            const int idx = t * 128 + tid;
            const int r   = idx >> 4;
            const int cc  = idx & 15;
            const uint32_t so = 2 * (r * FSTR + cc * 8);
            const size_t  go = ((size_t)h * T + q0 + r) * HD + cc * 8;
            CP16(sb + so,           g_q2h + go);
            CP16(sb + 2 * FQT + so, g_q2l + go);
        }
    };
    auto ldkv = [&](int kt2, int s) {
        const uint32_t kb = sb + 2 * (2 * FQT + (uint32_t)s * 4 * FKT);
#pragma unroll
        for (int t = 0; t < 4; t++) {
            const int idx = t * 128 + tid;
            const int r   = idx >> 4;
            const int cc  = idx & 15;
            const uint32_t so = 2 * (r * FSTR + cc * 8);
            const size_t  go = ((size_t)h * T + kt2 * 32 + r) * HD + cc * 8;
            CP16(kb + so,           g_k2h + go);
            CP16(kb + 2 * FKT + so, g_k2l + go);
            CP16(kb + 4 * FKT + so, g_v2h + go);
            CP16(kb + 6 * FKT + so, g_v2l + go);
        }
    };

    float acco[16][4];
#pragma unroll
    for (int nt = 0; nt < 16; nt++)
#pragma unroll
        for (int i = 0; i < 4; i++) acco[nt][i] = 0.f;
    float m0 = -1e30f, m1 = -1e30f, l0 = 0.f, l1 = 0.f;

    ldq(); ldkv(0, 0); CP_COMMIT();
    ldkv(1, 1); CP_COMMIT();

    const int r0l = wm * 16 + (lane >> 2);
    const int r1l = r0l + 8;
    const uint32_t qoff = 2 * ((wm * 16 + (lane & 15)) * FSTR + ((lane >> 4) << 3));
    const int krow = (lane & 7) + ((lane & 16) >> 1);
    const int rowMax = q0 + wm * 16 + 15;

    CP_WAIT(1);
    __syncthreads();
    uint32_t qh[8][4], ql[8][4];
#pragma unroll
    for (int j = 0; j < 8; j++) {
        const uint32_t qa = sb + qoff + 2 * (j * 16);
        LDSM4(qh[j][0], qh[j][1], qh[j][2], qh[j][3], qa);
        LDSM4(ql[j][0], ql[j][1], ql[j][2], ql[j][3], qa + 2 * FQT);
    }

    const int NKV = 2 * qt + 2;

    for (int kt = 0; kt < NKV; kt++) {
        if (kt > 0) {
            CP_WAIT(1);
            __syncthreads();
        }

        const bool active = (kt * 32 <= rowMax);
        const uint32_t kb = sb + 2 * (2 * FQT + (uint32_t)(kt & 1) * 4 * FKT);

        if (active) {
            float accA[4][4], accB[4][4];
#pragma unroll
            for (int nt = 0; nt < 4; nt++)
#pragma unroll
                for (int i = 0; i < 4; i++) { accA[nt][i] = 0.f; accB[nt][i] = 0.f; }

#pragma unroll
            for (int j = 0; j < 8; j++) {
                uint32_t bh[4][2], bl[4][2];
#pragma unroll
                for (int np = 0; np < 2; np++) {
                    const uint32_t ka = kb + 2 * ((np * 16 + krow) * FSTR + j * 16 + (lane & 8));
                    LDSM4(bh[2 * np][0], bh[2 * np][1], bh[2 * np + 1][0], bh[2 * np + 1][1], ka);
                    LDSM4(bl[2 * np][0], bl[2 * np][1], bl[2 * np + 1][0], bl[2 * np + 1][1],
                          ka + 2 * FKT);
                }
#pragma unroll
                for (int nt = 0; nt < 4; nt++) MMA16816(accA[nt], qh[j], bh[nt]);
#pragma unroll
                for (int nt = 0; nt < 4; nt++) MMA16816(accB[nt], qh[j], bl[nt]);
#pragma unroll
                for (int nt = 0; nt < 4; nt++) MMA16816(accB[nt], ql[j], bh[nt]);
            }

            float accs[4][4];
#pragma unroll
            for (int nt = 0; nt < 4; nt++)
#pragma unroll
                for (int i = 0; i < 4; i++) accs[nt][i] = accA[nt][i] + accB[nt][i];

            if (kt >= 2 * qt) {
                const int gr0 = q0 + r0l, gr1 = q0 + r1l;
#pragma unroll
                for (int nt = 0; nt < 4; nt++) {
                    const int c0 = kt * 32 + nt * 8 + 2 * (lane & 3);
                    if (c0     > gr0) accs[nt][0] = -1e30f;
                    if (c0 + 1 > gr0) accs[nt][1] = -1e30f;
                    if (c0     > gr1) accs[nt][2] = -1e30f;
                    if (c0 + 1 > gr1) accs[nt][3] = -1e30f;
                }
            }

            float mx0 = -1e30f, mx1 = -1e30f;
#pragma unroll
            for (int nt = 0; nt < 4; nt++) {
                mx0 = fmaxf(mx0, fmaxf(accs[nt][0], accs[nt][1]));
                mx1 = fmaxf(mx1, fmaxf(accs[nt][2], accs[nt][3]));
            }
            mx0 = fmaxf(mx0, __shfl_xor_sync(0xffffffffu, mx0, 1));
            mx0 = fmaxf(mx0, __shfl_xor_sync(0xffffffffu, mx0, 2));
            mx1 = fmaxf(mx1, __shfl_xor_sync(0xffffffffu, mx1, 1));
            mx1 = fmaxf(mx1, __shfl_xor_sync(0xffffffffu, mx1, 2));
            const float mn0 = fmaxf(m0, mx0), mn1 = fmaxf(m1, mx1);
            const float c0 = exp2f(m0 - mn0), c1 = exp2f(m1 - mn1);

            float p[4][4];
            float ps0 = 0.f, ps1 = 0.f;
#pragma unroll
            for (int nt = 0; nt < 4; nt++) {
                p[nt][0] = exp2f(accs[nt][0] - mn0); ps0 += p[nt][0];
                p[nt][1] = exp2f(accs[nt][1] - mn0); ps0 += p[nt][1];
                p[nt][2] = exp2f(accs[nt][2] - mn1); ps1 += p[nt][2];
                p[nt][3] = exp2f(accs[nt][3] - mn1); ps1 += p[nt][3];
            }
            ps0 += __shfl_xor_sync(0xffffffffu, ps0, 1);
            ps0 += __shfl_xor_sync(0xffffffffu, ps0, 2);
            ps1 += __shfl_xor_sync(0xffffffffu, ps1, 1);
            ps1 += __shfl_xor_sync(0xffffffffu, ps1, 2);
            l0 = l0 * c0 + ps0;
            l1 = l1 * c1 + ps1;
            m0 = mn0; m1 = mn1;

#pragma unroll
            for (int nt = 0; nt < 16; nt++) {
                acco[nt][0] *= c0; acco[nt][1] *= c0;
                acco[nt][2] *= c1; acco[nt][3] *= c1;
            }

            uint32_t pha[2][4], pla[2][4];
#pragma unroll
            for (int j = 0; j < 2; j++) {
                split2(p[2 * j][0],     p[2 * j][1],     pha[j][0], pla[j][0]);
                split2(p[2 * j][2],     p[2 * j][3],     pha[j][1], pla[j][1]);
                split2(p[2 * j + 1][0], p[2 * j + 1][1], pha[j][2], pla[j][2]);
                split2(p[2 * j + 1][2], p[2 * j + 1][3], pha[j][3], pla[j][3]);
            }

            const uint32_t vb = kb + 4 * FKT;
#pragma unroll
            for (int j = 0; j < 2; j++) {
                const int k0 = j * 16 + (lane & 15);
#pragma unroll
                for (int np = 0; np < 8; np++) {
                    const uint32_t va = vb + 2 * (k0 * FSTR + np * 16 + ((lane >> 4) << 3));
                    uint32_t vh[4], vl[4];
                    LDSM4T(vh[0], vh[1], vh[2], vh[3], va);
                    LDSM4T(vl[0], vl[1], vl[2], vl[3], va + 2 * FKT);
                    MMA16816(acco[2 * np],     pha[j], vh);
                    MMA16816(acco[2 * np + 1], pha[j], vh + 2);
                    MMA16816(acco[2 * np],     pha[j], vl);
                    MMA16816(acco[2 * np + 1], pha[j], vl + 2);
                    MMA16816(acco[2 * np],     pla[j], vh);
                    MMA16816(acco[2 * np + 1], pla[j], vh + 2);
                }
            }
        }

        __syncthreads();
        if (kt + 2 < NKV) ldkv(kt + 2, kt & 1);
        CP_COMMIT();
    }

    const float il0 = 1.f / l0, il1 = 1.f / l1;
#pragma unroll
    for (int nt = 0; nt < 16; nt++) {
        const int col = nt * 8 + 2 * (lane & 3);
        const float v0 = acco[nt][0] * il0;
        const float v1 = acco[nt][1] * il0;
        const float v2 = acco[nt][2] * il1;
        const float v3 = acco[nt][3] * il1;
        uint32_t hi, lo;
        const size_t o0 = (size_t)(q0 + r0l) * D + h * HD + col;
        const size_t o1 = (size_t)(q0 + r1l) * D + h * HD + col;
        split2(v0, v1, hi, lo);
        *(uint32_t*)&g_ah[o0] = hi; *(uint32_t*)&g_al[o0] = lo;
        split2(v2, v3, hi, lo);
        *(uint32_t*)&g_ah[o1] = hi; *(uint32_t*)&g_al[o1] = lo;
    }
}

// -----------------------------------------------------------------------------
extern "C" void kernel_launch(void* const* d_in, const int* in_sizes, int n_in,
                              void* d_out, int out_size)
{
    const float* x    = (const float*)d_in[0];
    const float* cosb = (const float*)d_in[1];
    const float* sinb = (const float*)d_in[2];
    const float* Wq   = (const float*)d_in[3];
    const float* Wk   = (const float*)d_in[4];
    const float* Wv   = (const float*)d_in[5];
    const float* Wo   = (const float*)d_in[6];
    const float* wq   = (const float*)d_in[7];
    const float* wk   = (const float*)d_in[8];
    const float* wv   = (const float*)d_in[9];
    const float* qnw  = (const float*)d_in[10];
    const float* knw  = (const float*)d_in[11];
    float* out = (float*)d_out;

    float *pq, *pk, *pv;
    __nv_bfloat16 *pxh, *pxl, *pwh, *pwl, *pah, *pal;
    cudaGetSymbolAddress((void**)&pq, g_q);
    cudaGetSymbolAddress((void**)&pk, g_k);
    cudaGetSymbolAddress((void**)&pv, g_v);
    cudaGetSymbolAddress((void**)&pxh, g_xh);
    cudaGetSymbolAddress((void**)&pxl, g_xl);
    cudaGetSymbolAddress((void**)&pwh, g_wh);
    cudaGetSymbolAddress((void**)&pwl, g_wl);
    cudaGetSymbolAddress((void**)&pah, g_ah);
    cudaGetSymbolAddress((void**)&pal, g_al);

    __nv_bfloat16* wh[4];
    __nv_bfloat16* wl[4];
    for (int i = 0; i < 4; i++) { wh[i] = pwh + (size_t)i * D * D; wl[i] = pwl + (size_t)i * D * D; }

    cudaFuncSetAttribute(gemm_bf16s, cudaFuncAttributeMaxDynamicSharedMemorySize, GEMM_SMEM);
    cudaFuncSetAttribute(flash_mma,  cudaFuncAttributeMaxDynamicSharedMemorySize, FSMEM);

    // 0) split x, Wq, Wk, Wv, Wo into bf16 hi/lo
    split_bf16<<<dim3(256, 1, 5), 256>>>(x, pxh, pxl,
                                         Wq, wh[0], wl[0],
                                         Wk, wh[1], wl[1],
                                         Wv, wh[2], wl[2],
                                         Wo, wh[3], wl[3]);

    // 1) QKV projections (256x128 tiles)
    gemm_bf16s<<<dim3(D / 128, T / 256, 3), 256, GEMM_SMEM>>>(pxh, pxl,
                                                    wh[0], wl[0], wh[1], wl[1], wh[2], wl[2],
                                                    pq, pk, pv);

    // 2) conv + SiLU + RMSNorm + RoPE + transpose (4 t per block)
    fuse_post<<<dim3(T / 4, H), HD>>>(cosb, sinb, wq, wk, wv, qnw, knw);

    // 3) causal flash attention
    flash_mma<<<dim3(T / 64, H), 128, FSMEM>>>();

    // 4) O-proj -> d_out
    gemm_bf16s<<<dim3(D / 128, T / 256, 1), 256, GEMM_SMEM>>>(pah, pal,
                                                    wh[3], wl[3], wh[3], wl[3], wh[3], wl[3],
                                                    out, out, out);
}

// round 15
// speedup vs baseline: 1.0533x; 1.0016x over previous
#include <cuda_runtime.h>
#include <cuda_bf16.h>
#include <math.h>
#include <stdint.h>

#define T 2048
#define D 2048
#define H 16
#define HD 128
#define RD 64
#define KC 4

// ---------------- scratch (device globals) -----------------------------------
__device__ float g_q[T * D];
__device__ float g_k[T * D];
__device__ float g_v[T * D];

__device__ __nv_bfloat16 g_xh[T * D], g_xl[T * D];
__device__ __nv_bfloat16 g_wh[4][D * D], g_wl[4][D * D];  // Wq,Wk,Wv,Wo
__device__ __nv_bfloat16 g_ah[T * D], g_al[T * D];        // attn out hi/lo

// flash inputs, bf16 hi/lo, [H][T][HD]
__device__ __nv_bfloat16 g_q2h[T * D], g_q2l[T * D];
__device__ __nv_bfloat16 g_k2h[T * D], g_k2l[T * D];
__device__ __nv_bfloat16 g_v2h[T * D], g_v2l[T * D];

// ---------------- PTX helpers --------------------------------------------------
__device__ __forceinline__ uint32_t smem_u32(const void* p) {
    uint32_t a;
    asm("{ .reg .u64 t; cvta.to.shared.u64 t, %1; cvt.u32.u64 %0, t; }" : "=r"(a) : "l"(p));
    return a;
}

#define CP16(dst, src) \
    asm volatile("cp.async.cg.shared.global [%0], [%1], 16;" :: "r"(dst), "l"(src))
#define CP_COMMIT() asm volatile("cp.async.commit_group;" ::: "memory")
#define CP_WAIT(n)  asm volatile("cp.async.wait_group %0;" :: "n"(n) : "memory")

#define LDSM4(r0, r1, r2, r3, addr)                                      \
    asm volatile("ldmatrix.sync.aligned.m8n8.x4.shared.b16 {%0,%1,%2,%3}, [%4];" \
        : "=r"(r0), "=r"(r1), "=r"(r2), "=r"(r3) : "r"(addr))

#define LDSM4T(r0, r1, r2, r3, addr)                                     \
    asm volatile("ldmatrix.sync.aligned.m8n8.x4.trans.shared.b16 {%0,%1,%2,%3}, [%4];" \
        : "=r"(r0), "=r"(r1), "=r"(r2), "=r"(r3) : "r"(addr))

#define MMA16816(d, a, b)                                                \
    asm volatile("mma.sync.aligned.m16n8k16.row.col.f32.bf16.bf16.f32 "  \
        "{%0,%1,%2,%3}, {%4,%5,%6,%7}, {%8,%9}, {%0,%1,%2,%3};"          \
        : "+f"((d)[0]), "+f"((d)[1]), "+f"((d)[2]), "+f"((d)[3])         \
        : "r"((a)[0]), "r"((a)[1]), "r"((a)[2]), "r"((a)[3]),            \
          "r"((b)[0]), "r"((b)[1]))

__device__ __forceinline__ void split2(float a, float b, uint32_t& hi, uint32_t& lo) {
    __nv_bfloat162 h = __floats2bfloat162_rn(a, b);
    __nv_bfloat162 l = __floats2bfloat162_rn(a - __low2float(h), b - __high2float(h));
    hi = *(uint32_t*)&h;
    lo = *(uint32_t*)&l;
}

// ---------------- fp32 -> bf16 hi/lo split (inputs) ----------------------------
__global__ void split_bf16(const float* __restrict__ s0, __nv_bfloat16* h0, __nv_bfloat16* l0,
                           const float* __restrict__ s1, __nv_bfloat16* h1, __nv_bfloat16* l1,
                           const float* __restrict__ s2, __nv_bfloat16* h2, __nv_bfloat16* l2,
                           const float* __restrict__ s3, __nv_bfloat16* h3, __nv_bfloat16* l3,
                           const float* __restrict__ s4, __nv_bfloat16* h4, __nv_bfloat16* l4)
{
    const float* s; __nv_bfloat16 *h, *l;
    switch (blockIdx.z) {
        case 0:  s = s0; h = h0; l = l0; break;
        case 1:  s = s1; h = h1; l = l1; break;
        case 2:  s = s2; h = h2; l = l2; break;
        case 3:  s = s3; h = h3; l = l3; break;
        default: s = s4; h = h4; l = l4; break;
    }
    const int n4 = T * D / 4;
    for (int i = blockIdx.x * blockDim.x + threadIdx.x; i < n4; i += gridDim.x * blockDim.x) {
        float4 v = ((const float4*)s)[i];
        __nv_bfloat162 h01 = __floats2bfloat162_rn(v.x, v.y);
        __nv_bfloat162 h23 = __floats2bfloat162_rn(v.z, v.w);
        __nv_bfloat162 l01 = __floats2bfloat162_rn(v.x - __low2float(h01), v.y - __high2float(h01));
        __nv_bfloat162 l23 = __floats2bfloat162_rn(v.z - __low2float(h23), v.w - __high2float(h23));
        ((__nv_bfloat162*)h)[2 * i]     = h01;
        ((__nv_bfloat162*)h)[2 * i + 1] = h23;
        ((__nv_bfloat162*)l)[2 * i]     = l01;
        ((__nv_bfloat162*)l)[2 * i + 1] = l23;
    }
}

// ---------------- bf16-split GEMM (NT), 256x128, late prefetch (best) ---------
#define BK      32
#define NCK     (D / BK)
#define TILE_AB (256 * 64)
#define TILE_BB (128 * 64)
#define STAGE_B (2 * TILE_AB + 2 * TILE_BB)
#define GEMM_SMEM (3 * STAGE_B)
#define SWZ16(row, ch) ((((ch) ^ (((row) >> 1) & 3))) * 16)

__global__ __launch_bounds__(256, 1)
void gemm_bf16s(const __nv_bfloat16* __restrict__ Ah_, const __nv_bfloat16* __restrict__ Al_,
                const __nv_bfloat16* __restrict__ Bh0, const __nv_bfloat16* __restrict__ Bl0,
                const __nv_bfloat16* __restrict__ Bh1, const __nv_bfloat16* __restrict__ Bl1,
                const __nv_bfloat16* __restrict__ Bh2, const __nv_bfloat16* __restrict__ Bl2,
                float* __restrict__ C0, float* __restrict__ C1, float* __restrict__ C2)
{
    const __nv_bfloat16* Bh_ = (blockIdx.z == 0) ? Bh0 : ((blockIdx.z == 1) ? Bh1 : Bh2);
    const __nv_bfloat16* Bl_ = (blockIdx.z == 0) ? Bl0 : ((blockIdx.z == 1) ? Bl1 : Bl2);
    float*               C   = (blockIdx.z == 0) ? C0  : ((blockIdx.z == 1) ? C1  : C2);

    extern __shared__ __nv_bfloat16 sm[];
    const uint32_t sbase = smem_u32(sm);

    const int tid  = threadIdx.x;
    const int lane = tid & 31;
    const int warp = tid >> 5;
    const int wm0  = (warp & 3) * 64;
    const int wn0  = (warp >> 2) * 64;
    const int brow = blockIdx.y * 256;
    const int bcol = blockIdx.x * 128;

    auto load_chunk = [&](int c, int slot) {
        const int k0 = c * BK;
        const uint32_t s0 = sbase + (uint32_t)slot * STAGE_B;
#pragma unroll
        for (int t = 0; t < 4; t++) {
            const int idx = t * 256 + tid;
            const int r   = idx >> 2;
            const int ch  = idx & 3;
            const uint32_t so = s0 + r * 64 + SWZ16(r, ch);
            const size_t ga = (size_t)(brow + r) * D + k0 + ch * 8;
            CP16(so,           Ah_ + ga);
            CP16(so + TILE_AB, Al_ + ga);
        }
#pragma unroll
        for (int t = 0; t < 2; t++) {
            const int idx = t * 256 + tid;
            const int r   = idx >> 2;
            const int ch  = idx & 3;
            const uint32_t so = s0 + 2 * TILE_AB + r * 64 + SWZ16(r, ch);
            const size_t gb = (size_t)(bcol + r) * D + k0 + ch * 8;
            CP16(so,           Bh_ + gb);
            CP16(so + TILE_BB, Bl_ + gb);
        }
    };

    float acc[4][8][4];
#pragma unroll
    for (int mt = 0; mt < 4; mt++)
#pragma unroll
        for (int nt = 0; nt < 8; nt++)
#pragma unroll
            for (int i = 0; i < 4; i++) acc[mt][nt][i] = 0.f;

    load_chunk(0, 0); CP_COMMIT();
    load_chunk(1, 1); CP_COMMIT();

    const int arow = wm0 + (lane & 15);
    const int achk = lane >> 4;
    const int nrow = wn0 + (lane & 7) + ((lane & 16) >> 1);
    const int bchk = (lane & 8) >> 3;

    for (int c = 0; c < NCK; c++) {
        CP_WAIT(1);
        __syncthreads();

        const uint32_t sbm = sbase + (uint32_t)(c % 3) * STAGE_B;
#pragma unroll
        for (int ks = 0; ks < 2; ks++) {
            uint32_t ah[4][4], al[4][4], bh[8][2], bl[8][2];
#pragma unroll
            for (int mt = 0; mt < 4; mt++) {
                const int lrow = arow + mt * 16;
                const uint32_t ad = sbm + lrow * 64 + SWZ16(lrow, ks * 2 + achk);
                LDSM4(ah[mt][0], ah[mt][1], ah[mt][2], ah[mt][3], ad);
                LDSM4(al[mt][0], al[mt][1], al[mt][2], al[mt][3], ad + TILE_AB);
            }
#pragma unroll
            for (int np = 0; np < 4; np++) {
                const int brw = nrow + np * 16;
                const uint32_t bd = sbm + 2 * TILE_AB + brw * 64 + SWZ16(brw, ks * 2 + bchk);
                LDSM4(bh[2 * np][0], bh[2 * np][1], bh[2 * np + 1][0], bh[2 * np + 1][1], bd);
                LDSM4(bl[2 * np][0], bl[2 * np][1], bl[2 * np + 1][0], bl[2 * np + 1][1],
                      bd + TILE_BB);
            }
#pragma unroll
            for (int mt = 0; mt < 4; mt++)
#pragma unroll
                for (int nt = 0; nt < 8; nt++) MMA16816(acc[mt][nt], ah[mt], bh[nt]);
#pragma unroll
            for (int mt = 0; mt < 4; mt++)
#pragma unroll
                for (int nt = 0; nt < 8; nt++) MMA16816(acc[mt][nt], ah[mt], bl[nt]);
#pragma unroll
            for (int mt = 0; mt < 4; mt++)
#pragma unroll
                for (int nt = 0; nt < 8; nt++) MMA16816(acc[mt][nt], al[mt], bh[nt]);
        }

        if (c + 2 < NCK) load_chunk(c + 2, (c + 2) % 3);
        CP_COMMIT();
    }

#pragma unroll
    for (int mt = 0; mt < 4; mt++) {
        const int row = brow + wm0 + mt * 16 + (lane >> 2);
#pragma unroll
        for (int nt = 0; nt < 8; nt++) {
            const int col = bcol + wn0 + nt * 8 + 2 * (lane & 3);
            float* p = C + (size_t)row * D + col;
            p[0] = acc[mt][nt][0];
            p[1] = acc[mt][nt][1];
            p += 8 * (size_t)D;
            p[0] = acc[mt][nt][2];
            p[1] = acc[mt][nt][3];
        }
    }
}

// -------- fused post v2: 4 t-values per block ---------------------------------
__global__ void fuse_post(const float* __restrict__ cosb,
                          const float* __restrict__ sinb,
                          const float* __restrict__ wq,
                          const float* __restrict__ wk,
                          const float* __restrict__ wv,
                          const float* __restrict__ qnw,
                          const float* __restrict__ knw)
{
    const int t0 = blockIdx.x * 4;
    const int h  = blockIdx.y;
    const int hd = threadIdx.x;
    const int d  = h * HD + hd;

    float xq[7], xk[7], xv[7];
#pragma unroll
    for (int i = 0; i < 7; i++) {
        const int tt = t0 - 3 + i;
        if (tt >= 0) {
            const size_t o = (size_t)tt * D + d;
            xq[i] = g_q[o]; xk[i] = g_k[o]; xv[i] = g_v[o];
        } else {
            xq[i] = 0.f; xk[i] = 0.f; xv[i] = 0.f;
        }
    }
    float wqr[4], wkr[4], wvr[4];
#pragma unroll
    for (int j = 0; j < 4; j++) {
        wqr[j] = wq[d * KC + j]; wkr[j] = wk[d * KC + j]; wvr[j] = wv[d * KC + j];
    }

    float yq[4], yk[4], yv[4];
#pragma unroll
    for (int ti = 0; ti < 4; ti++) {
        float aq = 0.f, ak = 0.f, av = 0.f;
#pragma unroll
        for (int j = 0; j < 4; j++) {
            aq = fmaf(xq[ti + j], wqr[j], aq);
            ak = fmaf(xk[ti + j], wkr[j], ak);
            av = fmaf(xv[ti + j], wvr[j], av);
        }
        yq[ti] = aq / (1.f + __expf(-aq));
        yk[ti] = ak / (1.f + __expf(-ak));
        yv[ti] = av / (1.f + __expf(-av));
    }

    __shared__ float rq[4][4], rk[4][4], sq[4][HD], sk[4][HD];
    const int w = hd >> 5;
    float vq[4], vk[4];
#pragma unroll
    for (int ti = 0; ti < 4; ti++) { vq[ti] = yq[ti] * yq[ti]; vk[ti] = yk[ti] * yk[ti]; }
#pragma unroll
    for (int off = 16; off > 0; off >>= 1) {
#pragma unroll
        for (int ti = 0; ti < 4; ti++) {
            vq[ti] += __shfl_xor_sync(0xffffffffu, vq[ti], off);
            vk[ti] += __shfl_xor_sync(0xffffffffu, vk[ti], off);
        }
    }
    if ((hd & 31) == 0) {
#pragma unroll
        for (int ti = 0; ti < 4; ti++) { rq[ti][w] = vq[ti]; rk[ti][w] = vk[ti]; }
    }
    __syncthreads();
#pragma unroll
    for (int ti = 0; ti < 4; ti++) {
        const float varq = (rq[ti][0] + rq[ti][1] + rq[ti][2] + rq[ti][3]) * (1.f / HD);
        const float vark = (rk[ti][0] + rk[ti][1] + rk[ti][2] + rk[ti][3]) * (1.f / HD);
        sq[ti][hd] = yq[ti] * rsqrtf(varq + 1e-5f) * qnw[hd];
        sk[ti][hd] = yk[ti] * rsqrtf(vark + 1e-5f) * knw[hd];
    }
    __syncthreads();

    const float scale = 0.08838834764831845f * 1.4426950408889634f;

#pragma unroll
    for (int ti = 0; ti < 4; ti++) {
        const int t = t0 + ti;
        float oq, ok;
        if (hd < RD) {
            const float cs = cosb[t * RD + hd];
            const float sn = sinb[t * RD + hd];
            const float rqv = (hd < RD / 2) ? -sq[ti][hd + RD / 2] : sq[ti][hd - RD / 2];
            const float rkv = (hd < RD / 2) ? -sk[ti][hd + RD / 2] : sk[ti][hd - RD / 2];
            oq = -(sq[ti][hd] * cs + rqv * sn);
            ok = -(sk[ti][hd] * cs + rkv * sn);
        } else {
            oq = sq[ti][hd];
            ok = sk[ti][hd];
        }
        oq *= scale;

        const size_t o = ((size_t)h * T + t) * HD + hd;
        __nv_bfloat16 b;
        b = __float2bfloat16(oq);
        g_q2h[o] = b; g_q2l[o] = __float2bfloat16(oq - __bfloat162float(b));
        b = __float2bfloat16(ok);
        g_k2h[o] = b; g_k2l[o] = __float2bfloat16(ok - __bfloat162float(b));
        b = __float2bfloat16(yv[ti]);
        g_v2h[o] = b; g_v2l[o] = __float2bfloat16(yv[ti] - __bfloat162float(b));
    }
}

// ---------------- flash attention (best-known form) ---------------------------
#define FSTR   136
#define FQT    (64 * FSTR)
#define FKT    (32 * FSTR)
#define FSMEM  ((2 * FQT + 8 * FKT) * 2)  // 104448 B -> 2 CTAs/SM

__global__ __launch_bounds__(128, 2)
void flash_mma()
{
    extern __shared__ __nv_bfloat16 fsm[];

    const int tid  = threadIdx.x;
    const int lane = tid & 31;
    const int wm   = tid >> 5;
    const int h    = blockIdx.y;
    const int qt   = gridDim.x - 1 - blockIdx.x;
    const int q0   = qt * 64;

    const uint32_t sb = smem_u32(fsm);

    auto ldq = [&]() {
#pragma unroll
        for (int t = 0; t < 8; t++) {
            const int idx = t * 128 + tid;
            const int r   = idx >> 4;
            const int cc  = idx & 15;
            const uint32_t so = 2 * (r * FSTR + cc * 8);
            const size_t  go = ((size_t)h * T + q0 + r) * HD + cc * 8;
            CP16(sb + so,           g_q2h + go);
            CP16(sb + 2 * FQT + so, g_q2l + go);
        }
    };
    auto ldkv = [&](int kt2, int s) {
        const uint32_t kb = sb + 2 * (2 * FQT + (uint32_t)s * 4 * FKT);
#pragma unroll
        for (int t = 0; t < 4; t++) {
            const int idx = t * 128 + tid;
            const int r   = idx >> 4;
            const int cc  = idx & 15;
            const uint32_t so = 2 * (r * FSTR + cc * 8);
            const size_t  go = ((size_t)h * T + kt2 * 32 + r) * HD + cc * 8;
            CP16(kb + so,           g_k2h + go);
            CP16(kb + 2 * FKT + so, g_k2l + go);
            CP16(kb + 4 * FKT + so, g_v2h + go);
            CP16(kb + 6 * FKT + so, g_v2l + go);
        }
    };

    float acco[16][4];
#pragma unroll
    for (int nt = 0; nt < 16; nt++)
#pragma unroll
        for (int i = 0; i < 4; i++) acco[nt][i] = 0.f;
    float m0 = -1e30f, m1 = -1e30f, l0 = 0.f, l1 = 0.f;

    ldq(); ldkv(0, 0); CP_COMMIT();
    ldkv(1, 1); CP_COMMIT();

    const int r0l = wm * 16 + (lane >> 2);
    const int r1l = r0l + 8;
    const uint32_t qoff = 2 * ((wm * 16 + (lane & 15)) * FSTR + ((lane >> 4) << 3));
    const int krow = (lane & 7) + ((lane & 16) >> 1);
    const int rowMax = q0 + wm * 16 + 15;

    CP_WAIT(1);
    __syncthreads();
    uint32_t qh[8][4], ql[8][4];
#pragma unroll
    for (int j = 0; j < 8; j++) {
        const uint32_t qa = sb + qoff + 2 * (j * 16);
        LDSM4(qh[j][0], qh[j][1], qh[j][2], qh[j][3], qa);
        LDSM4(ql[j][0], ql[j][1], ql[j][2], ql[j][3], qa + 2 * FQT);
    }

    const int NKV = 2 * qt + 2;

    for (int kt = 0; kt < NKV; kt++) {
        if (kt > 0) {
            CP_WAIT(1);
            __syncthreads();
        }

        const bool active = (kt * 32 <= rowMax);
        const uint32_t kb = sb + 2 * (2 * FQT + (uint32_t)(kt & 1) * 4 * FKT);

        if (active) {
            float accA[4][4], accB[4][4];
#pragma unroll
            for (int nt = 0; nt < 4; nt++)
#pragma unroll
                for (int i = 0; i < 4; i++) { accA[nt][i] = 0.f; accB[nt][i] = 0.f; }

#pragma unroll
            for (int j = 0; j < 8; j++) {
                uint32_t bh[4][2], bl[4][2];
#pragma unroll
                for (int np = 0; np < 2; np++) {
                    const uint32_t ka = kb + 2 * ((np * 16 + krow) * FSTR + j * 16 + (lane & 8));
                    LDSM4(bh[2 * np][0], bh[2 * np][1], bh[2 * np + 1][0], bh[2 * np + 1][1], ka);
                    LDSM4(bl[2 * np][0], bl[2 * np][1], bl[2 * np + 1][0], bl[2 * np + 1][1],
                          ka + 2 * FKT);
                }
#pragma unroll
                for (int nt = 0; nt < 4; nt++) MMA16816(accA[nt], qh[j], bh[nt]);
#pragma unroll
                for (int nt = 0; nt < 4; nt++) MMA16816(accB[nt], qh[j], bl[nt]);
#pragma unroll
                for (int nt = 0; nt < 4; nt++) MMA16816(accB[nt], ql[j], bh[nt]);
            }

            float accs[4][4];
#pragma unroll
            for (int nt = 0; nt < 4; nt++)
#pragma unroll
                for (int i = 0; i < 4; i++) accs[nt][i] = accA[nt][i] + accB[nt][i];

            if (kt >= 2 * qt) {
                const int gr0 = q0 + r0l, gr1 = q0 + r1l;
#pragma unroll
                for (int nt = 0; nt < 4; nt++) {
                    const int c0 = kt * 32 + nt * 8 + 2 * (lane & 3);
                    if (c0     > gr0) accs[nt][0] = -1e30f;
                    if (c0 + 1 > gr0) accs[nt][1] = -1e30f;
                    if (c0     > gr1) accs[nt][2] = -1e30f;
                    if (c0 + 1 > gr1) accs[nt][3] = -1e30f;
                }
            }

            float mx0 = -1e30f, mx1 = -1e30f;
#pragma unroll
            for (int nt = 0; nt < 4; nt++) {
                mx0 = fmaxf(mx0, fmaxf(accs[nt][0], accs[nt][1]));
                mx1 = fmaxf(mx1, fmaxf(accs[nt][2], accs[nt][3]));
            }
            mx0 = fmaxf(mx0, __shfl_xor_sync(0xffffffffu, mx0, 1));
            mx0 = fmaxf(mx0, __shfl_xor_sync(0xffffffffu, mx0, 2));
            mx1 = fmaxf(mx1, __shfl_xor_sync(0xffffffffu, mx1, 1));
            mx1 = fmaxf(mx1, __shfl_xor_sync(0xffffffffu, mx1, 2));
            const float mn0 = fmaxf(m0, mx0), mn1 = fmaxf(m1, mx1);
            const float c0 = exp2f(m0 - mn0), c1 = exp2f(m1 - mn1);

            float p[4][4];
            float ps0 = 0.f, ps1 = 0.f;
#pragma unroll
            for (int nt = 0; nt < 4; nt++) {
                p[nt][0] = exp2f(accs[nt][0] - mn0); ps0 += p[nt][0];
                p[nt][1] = exp2f(accs[nt][1] - mn0); ps0 += p[nt][1];
                p[nt][2] = exp2f(accs[nt][2] - mn1); ps1 += p[nt][2];
                p[nt][3] = exp2f(accs[nt][3] - mn1); ps1 += p[nt][3];
            }
            ps0 += __shfl_xor_sync(0xffffffffu, ps0, 1);
            ps0 += __shfl_xor_sync(0xffffffffu, ps0, 2);
            ps1 += __shfl_xor_sync(0xffffffffu, ps1, 1);
            ps1 += __shfl_xor_sync(0xffffffffu, ps1, 2);
            l0 = l0 * c0 + ps0;
            l1 = l1 * c1 + ps1;
            m0 = mn0; m1 = mn1;

#pragma unroll
            for (int nt = 0; nt < 16; nt++) {
                acco[nt][0] *= c0; acco[nt][1] *= c0;
                acco[nt][2] *= c1; acco[nt][3] *= c1;
            }

            uint32_t pha[2][4], pla[2][4];
#pragma unroll
            for (int j = 0; j < 2; j++) {
                split2(p[2 * j][0],     p[2 * j][1],     pha[j][0], pla[j][0]);
                split2(p[2 * j][2],     p[2 * j][3],     pha[j][1], pla[j][1]);
                split2(p[2 * j + 1][0], p[2 * j + 1][1], pha[j][2], pla[j][2]);
                split2(p[2 * j + 1][2], p[2 * j + 1][3], pha[j][3], pla[j][3]);
            }

            const uint32_t vb = kb + 4 * FKT;
#pragma unroll
            for (int j = 0; j < 2; j++) {
                const int k0 = j * 16 + (lane & 15);
#pragma unroll
                for (int np = 0; np < 8; np++) {
                    const uint32_t va = vb + 2 * (k0 * FSTR + np * 16 + ((lane >> 4) << 3));
                    uint32_t vh[4], vl[4];
                    LDSM4T(vh[0], vh[1], vh[2], vh[3], va);
                    LDSM4T(vl[0], vl[1], vl[2], vl[3], va + 2 * FKT);
                    MMA16816(acco[2 * np],     pha[j], vh);
                    MMA16816(acco[2 * np + 1], pha[j], vh + 2);
                    MMA16816(acco[2 * np],     pha[j], vl);
                    MMA16816(acco[2 * np + 1], pha[j], vl + 2);
                    MMA16816(acco[2 * np],     pla[j], vh);
                    MMA16816(acco[2 * np + 1], pla[j], vh + 2);
                }
            }
        }

        __syncthreads();
        if (kt + 2 < NKV) ldkv(kt + 2, kt & 1);
        CP_COMMIT();
    }

    const float il0 = 1.f / l0, il1 = 1.f / l1;
#pragma unroll
    for (int nt = 0; nt < 16; nt++) {
        const int col = nt * 8 + 2 * (lane & 3);
        const float v0 = acco[nt][0] * il0;
        const float v1 = acco[nt][1] * il0;
        const float v2 = acco[nt][2] * il1;
        const float v3 = acco[nt][3] * il1;
        uint32_t hi, lo;
        const size_t o0 = (size_t)(q0 + r0l) * D + h * HD + col;
        const size_t o1 = (size_t)(q0 + r1l) * D + h * HD + col;
        split2(v0, v1, hi, lo);
        *(uint32_t*)&g_ah[o0] = hi; *(uint32_t*)&g_al[o0] = lo;
        split2(v2, v3, hi, lo);
        *(uint32_t*)&g_ah[o1] = hi; *(uint32_t*)&g_al[o1] = lo;
    }
}

// -----------------------------------------------------------------------------
extern "C" void kernel_launch(void* const* d_in, const int* in_sizes, int n_in,
                              void* d_out, int out_size)
{
    const float* x    = (const float*)d_in[0];
    const float* cosb = (const float*)d_in[1];
    const float* sinb = (const float*)d_in[2];
    const float* Wq   = (const float*)d_in[3];
    const float* Wk   = (const float*)d_in[4];
    const float* Wv   = (const float*)d_in[5];
    const float* Wo   = (const float*)d_in[6];
    const float* wq   = (const float*)d_in[7];
    const float* wk   = (const float*)d_in[8];
    const float* wv   = (const float*)d_in[9];
    const float* qnw  = (const float*)d_in[10];
    const float* knw  = (const float*)d_in[11];
    float* out = (float*)d_out;

    float *pq, *pk, *pv;
    __nv_bfloat16 *pxh, *pxl, *pwh, *pwl, *pah, *pal;
    cudaGetSymbolAddress((void**)&pq, g_q);
    cudaGetSymbolAddress((void**)&pk, g_k);
    cudaGetSymbolAddress((void**)&pv, g_v);
    cudaGetSymbolAddress((void**)&pxh, g_xh);
    cudaGetSymbolAddress((void**)&pxl, g_xl);
    cudaGetSymbolAddress((void**)&pwh, g_wh);
    cudaGetSymbolAddress((void**)&pwl, g_wl);
    cudaGetSymbolAddress((void**)&pah, g_ah);
    cudaGetSymbolAddress((void**)&pal, g_al);

    __nv_bfloat16* wh[4];
    __nv_bfloat16* wl[4];
    for (int i = 0; i < 4; i++) { wh[i] = pwh + (size_t)i * D * D; wl[i] = pwl + (size_t)i * D * D; }

    cudaFuncSetAttribute(gemm_bf16s, cudaFuncAttributeMaxDynamicSharedMemorySize, GEMM_SMEM);
    cudaFuncSetAttribute(flash_mma,  cudaFuncAttributeMaxDynamicSharedMemorySize, FSMEM);

    // 0) split x, Wq, Wk, Wv, Wo into bf16 hi/lo
    split_bf16<<<dim3(256, 1, 5), 256>>>(x, pxh, pxl,
                                         Wq, wh[0], wl[0],
                                         Wk, wh[1], wl[1],
                                         Wv, wh[2], wl[2],
                                         Wo, wh[3], wl[3]);

    // 1) QKV projections (256x128 tiles)
    gemm_bf16s<<<dim3(D / 128, T / 256, 3), 256, GEMM_SMEM>>>(pxh, pxl,
                                                    wh[0], wl[0], wh[1], wl[1], wh[2], wl[2],
                                                    pq, pk, pv);

    // 2) conv + SiLU + RMSNorm + RoPE + transpose (4 t per block)
    fuse_post<<<dim3(T / 4, H), HD>>>(cosb, sinb, wq, wk, wv, qnw, knw);

    // 3) causal flash attention
    flash_mma<<<dim3(T / 64, H), 128, FSMEM>>>();

    // 4) O-proj -> d_out
    gemm_bf16s<<<dim3(D / 128, T / 256, 1), 256, GEMM_SMEM>>>(pah, pal,
                                                    wh[3], wl[3], wh[3], wl[3], wh[3], wl[3],
                                                    out, out, out);
}

// round 16
// speedup vs baseline: 1.0604x; 1.0067x over previous
#include <cuda_runtime.h>
#include <cuda_bf16.h>
#include <math.h>
#include <stdint.h>

#define T 2048
#define D 2048
#define H 16
#define HD 128
#define RD 64
#define KC 4

// ---------------- scratch (device globals) -----------------------------------
__device__ float g_q[T * D];
__device__ float g_k[T * D];
__device__ float g_v[T * D];

__device__ __nv_bfloat16 g_xh[T * D], g_xl[T * D];
__device__ __nv_bfloat16 g_wh[4][D * D], g_wl[4][D * D];  // Wq,Wk,Wv,Wo
__device__ __nv_bfloat16 g_ah[T * D], g_al[T * D];        // attn out hi/lo

// flash inputs, bf16 hi/lo, [H][T][HD]
__device__ __nv_bfloat16 g_q2h[T * D], g_q2l[T * D];
__device__ __nv_bfloat16 g_k2h[T * D], g_k2l[T * D];
__device__ __nv_bfloat16 g_v2h[T * D], g_v2l[T * D];

// ---------------- PTX helpers --------------------------------------------------
__device__ __forceinline__ uint32_t smem_u32(const void* p) {
    uint32_t a;
    asm("{ .reg .u64 t; cvta.to.shared.u64 t, %1; cvt.u32.u64 %0, t; }" : "=r"(a) : "l"(p));
    return a;
}

#define CP16(dst, src) \
    asm volatile("cp.async.cg.shared.global [%0], [%1], 16;" :: "r"(dst), "l"(src))
#define CP_COMMIT() asm volatile("cp.async.commit_group;" ::: "memory")
#define CP_WAIT(n)  asm volatile("cp.async.wait_group %0;" :: "n"(n) : "memory")

#define LDSM4(r0, r1, r2, r3, addr)                                      \
    asm volatile("ldmatrix.sync.aligned.m8n8.x4.shared.b16 {%0,%1,%2,%3}, [%4];" \
        : "=r"(r0), "=r"(r1), "=r"(r2), "=r"(r3) : "r"(addr))

#define LDSM4T(r0, r1, r2, r3, addr)                                     \
    asm volatile("ldmatrix.sync.aligned.m8n8.x4.trans.shared.b16 {%0,%1,%2,%3}, [%4];" \
        : "=r"(r0), "=r"(r1), "=r"(r2), "=r"(r3) : "r"(addr))

#define MMA16816(d, a, b)                                                \
    asm volatile("mma.sync.aligned.m16n8k16.row.col.f32.bf16.bf16.f32 "  \
        "{%0,%1,%2,%3}, {%4,%5,%6,%7}, {%8,%9}, {%0,%1,%2,%3};"          \
        : "+f"((d)[0]), "+f"((d)[1]), "+f"((d)[2]), "+f"((d)[3])         \
        : "r"((a)[0]), "r"((a)[1]), "r"((a)[2]), "r"((a)[3]),            \
          "r"((b)[0]), "r"((b)[1]))

__device__ __forceinline__ void split2(float a, float b, uint32_t& hi, uint32_t& lo) {
    __nv_bfloat162 h = __floats2bfloat162_rn(a, b);
    __nv_bfloat162 l = __floats2bfloat162_rn(a - __low2float(h), b - __high2float(h));
    hi = *(uint32_t*)&h;
    lo = *(uint32_t*)&l;
}

// ---------------- fp32 -> bf16 hi/lo split (inputs) ----------------------------
__global__ void split_bf16(const float* __restrict__ s0, __nv_bfloat16* h0, __nv_bfloat16* l0,
                           const float* __restrict__ s1, __nv_bfloat16* h1, __nv_bfloat16* l1,
                           const float* __restrict__ s2, __nv_bfloat16* h2, __nv_bfloat16* l2,
                           const float* __restrict__ s3, __nv_bfloat16* h3, __nv_bfloat16* l3,
                           const float* __restrict__ s4, __nv_bfloat16* h4, __nv_bfloat16* l4)
{
    const float* s; __nv_bfloat16 *h, *l;
    switch (blockIdx.z) {
        case 0:  s = s0; h = h0; l = l0; break;
        case 1:  s = s1; h = h1; l = l1; break;
        case 2:  s = s2; h = h2; l = l2; break;
        case 3:  s = s3; h = h3; l = l3; break;
        default: s = s4; h = h4; l = l4; break;
    }
    const int n4 = T * D / 4;
    for (int i = blockIdx.x * blockDim.x + threadIdx.x; i < n4; i += gridDim.x * blockDim.x) {
        float4 v = ((const float4*)s)[i];
        __nv_bfloat162 h01 = __floats2bfloat162_rn(v.x, v.y);
        __nv_bfloat162 h23 = __floats2bfloat162_rn(v.z, v.w);
        __nv_bfloat162 l01 = __floats2bfloat162_rn(v.x - __low2float(h01), v.y - __high2float(h01));
        __nv_bfloat162 l23 = __floats2bfloat162_rn(v.z - __low2float(h23), v.w - __high2float(h23));
        ((__nv_bfloat162*)h)[2 * i]     = h01;
        ((__nv_bfloat162*)h)[2 * i + 1] = h23;
        ((__nv_bfloat162*)l)[2 * i]     = l01;
        ((__nv_bfloat162*)l)[2 * i + 1] = l23;
    }
}

// ---------------- bf16-split GEMM (NT), 256x128, late prefetch (best) ---------
#define BK      32
#define NCK     (D / BK)
#define TILE_AB (256 * 64)
#define TILE_BB (128 * 64)
#define STAGE_B (2 * TILE_AB + 2 * TILE_BB)
#define GEMM_SMEM (3 * STAGE_B)
#define SWZ16(row, ch) ((((ch) ^ (((row) >> 1) & 3))) * 16)

__global__ __launch_bounds__(256, 1)
void gemm_bf16s(const __nv_bfloat16* __restrict__ Ah_, const __nv_bfloat16* __restrict__ Al_,
                const __nv_bfloat16* __restrict__ Bh0, const __nv_bfloat16* __restrict__ Bl0,
                const __nv_bfloat16* __restrict__ Bh1, const __nv_bfloat16* __restrict__ Bl1,
                const __nv_bfloat16* __restrict__ Bh2, const __nv_bfloat16* __restrict__ Bl2,
                float* __restrict__ C0, float* __restrict__ C1, float* __restrict__ C2)
{
    const __nv_bfloat16* Bh_ = (blockIdx.z == 0) ? Bh0 : ((blockIdx.z == 1) ? Bh1 : Bh2);
    const __nv_bfloat16* Bl_ = (blockIdx.z == 0) ? Bl0 : ((blockIdx.z == 1) ? Bl1 : Bl2);
    float*               C   = (blockIdx.z == 0) ? C0  : ((blockIdx.z == 1) ? C1  : C2);

    extern __shared__ __nv_bfloat16 sm[];
    const uint32_t sbase = smem_u32(sm);

    const int tid  = threadIdx.x;
    const int lane = tid & 31;
    const int warp = tid >> 5;
    const int wm0  = (warp & 3) * 64;
    const int wn0  = (warp >> 2) * 64;
    const int brow = blockIdx.y * 256;
    const int bcol = blockIdx.x * 128;

    auto load_chunk = [&](int c, int slot) {
        const int k0 = c * BK;
        const uint32_t s0 = sbase + (uint32_t)slot * STAGE_B;
#pragma unroll
        for (int t = 0; t < 4; t++) {
            const int idx = t * 256 + tid;
            const int r   = idx >> 2;
            const int ch  = idx & 3;
            const uint32_t so = s0 + r * 64 + SWZ16(r, ch);
            const size_t ga = (size_t)(brow + r) * D + k0 + ch * 8;
            CP16(so,           Ah_ + ga);
            CP16(so + TILE_AB, Al_ + ga);
        }
#pragma unroll
        for (int t = 0; t < 2; t++) {
            const int idx = t * 256 + tid;
            const int r   = idx >> 2;
            const int ch  = idx & 3;
            const uint32_t so = s0 + 2 * TILE_AB + r * 64 + SWZ16(r, ch);
            const size_t gb = (size_t)(bcol + r) * D + k0 + ch * 8;
            CP16(so,           Bh_ + gb);
            CP16(so + TILE_BB, Bl_ + gb);
        }
    };

    float acc[4][8][4];
#pragma unroll
    for (int mt = 0; mt < 4; mt++)
#pragma unroll
        for (int nt = 0; nt < 8; nt++)
#pragma unroll
            for (int i = 0; i < 4; i++) acc[mt][nt][i] = 0.f;

    load_chunk(0, 0); CP_COMMIT();
    load_chunk(1, 1); CP_COMMIT();

    const int arow = wm0 + (lane & 15);
    const int achk = lane >> 4;
    const int nrow = wn0 + (lane & 7) + ((lane & 16) >> 1);
    const int bchk = (lane & 8) >> 3;

    for (int c = 0; c < NCK; c++) {
        CP_WAIT(1);
        __syncthreads();

        const uint32_t sbm = sbase + (uint32_t)(c % 3) * STAGE_B;
#pragma unroll
        for (int ks = 0; ks < 2; ks++) {
            uint32_t ah[4][4], al[4][4], bh[8][2], bl[8][2];
#pragma unroll
            for (int mt = 0; mt < 4; mt++) {
                const int lrow = arow + mt * 16;
                const uint32_t ad = sbm + lrow * 64 + SWZ16(lrow, ks * 2 + achk);
                LDSM4(ah[mt][0], ah[mt][1], ah[mt][2], ah[mt][3], ad);
                LDSM4(al[mt][0], al[mt][1], al[mt][2], al[mt][3], ad + TILE_AB);
            }
#pragma unroll
            for (int np = 0; np < 4; np++) {
                const int brw = nrow + np * 16;
                const uint32_t bd = sbm + 2 * TILE_AB + brw * 64 + SWZ16(brw, ks * 2 + bchk);
                LDSM4(bh[2 * np][0], bh[2 * np][1], bh[2 * np + 1][0], bh[2 * np + 1][1], bd);
                LDSM4(bl[2 * np][0], bl[2 * np][1], bl[2 * np + 1][0], bl[2 * np + 1][1],
                      bd + TILE_BB);
            }
#pragma unroll
            for (int mt = 0; mt < 4; mt++)
#pragma unroll
                for (int nt = 0; nt < 8; nt++) MMA16816(acc[mt][nt], ah[mt], bh[nt]);
#pragma unroll
            for (int mt = 0; mt < 4; mt++)
#pragma unroll
                for (int nt = 0; nt < 8; nt++) MMA16816(acc[mt][nt], ah[mt], bl[nt]);
#pragma unroll
            for (int mt = 0; mt < 4; mt++)
#pragma unroll
                for (int nt = 0; nt < 8; nt++) MMA16816(acc[mt][nt], al[mt], bh[nt]);
        }

        if (c + 2 < NCK) load_chunk(c + 2, (c + 2) % 3);
        CP_COMMIT();
    }

#pragma unroll
    for (int mt = 0; mt < 4; mt++) {
        const int row = brow + wm0 + mt * 16 + (lane >> 2);
#pragma unroll
        for (int nt = 0; nt < 8; nt++) {
            const int col = bcol + wn0 + nt * 8 + 2 * (lane & 3);
            float* p = C + (size_t)row * D + col;
            p[0] = acc[mt][nt][0];
            p[1] = acc[mt][nt][1];
            p += 8 * (size_t)D;
            p[0] = acc[mt][nt][2];
            p[1] = acc[mt][nt][3];
        }
    }
}

// -------- fused post v2: 4 t-values per block ---------------------------------
__global__ void fuse_post(const float* __restrict__ cosb,
                          const float* __restrict__ sinb,
                          const float* __restrict__ wq,
                          const float* __restrict__ wk,
                          const float* __restrict__ wv,
                          const float* __restrict__ qnw,
                          const float* __restrict__ knw)
{
    const int t0 = blockIdx.x * 4;
    const int h  = blockIdx.y;
    const int hd = threadIdx.x;
    const int d  = h * HD + hd;

    float xq[7], xk[7], xv[7];
#pragma unroll
    for (int i = 0; i < 7; i++) {
        const int tt = t0 - 3 + i;
        if (tt >= 0) {
            const size_t o = (size_t)tt * D + d;
            xq[i] = g_q[o]; xk[i] = g_k[o]; xv[i] = g_v[o];
        } else {
            xq[i] = 0.f; xk[i] = 0.f; xv[i] = 0.f;
        }
    }
    float wqr[4], wkr[4], wvr[4];
#pragma unroll
    for (int j = 0; j < 4; j++) {
        wqr[j] = wq[d * KC + j]; wkr[j] = wk[d * KC + j]; wvr[j] = wv[d * KC + j];
    }

    float yq[4], yk[4], yv[4];
#pragma unroll
    for (int ti = 0; ti < 4; ti++) {
        float aq = 0.f, ak = 0.f, av = 0.f;
#pragma unroll
        for (int j = 0; j < 4; j++) {
            aq = fmaf(xq[ti + j], wqr[j], aq);
            ak = fmaf(xk[ti + j], wkr[j], ak);
            av = fmaf(xv[ti + j], wvr[j], av);
        }
        yq[ti] = aq / (1.f + __expf(-aq));
        yk[ti] = ak / (1.f + __expf(-ak));
        yv[ti] = av / (1.f + __expf(-av));
    }

    __shared__ float rq[4][4], rk[4][4], sq[4][HD], sk[4][HD];
    const int w = hd >> 5;
    float vq[4], vk[4];
#pragma unroll
    for (int ti = 0; ti < 4; ti++) { vq[ti] = yq[ti] * yq[ti]; vk[ti] = yk[ti] * yk[ti]; }
#pragma unroll
    for (int off = 16; off > 0; off >>= 1) {
#pragma unroll
        for (int ti = 0; ti < 4; ti++) {
            vq[ti] += __shfl_xor_sync(0xffffffffu, vq[ti], off);
            vk[ti] += __shfl_xor_sync(0xffffffffu, vk[ti], off);
        }
    }
    if ((hd & 31) == 0) {
#pragma unroll
        for (int ti = 0; ti < 4; ti++) { rq[ti][w] = vq[ti]; rk[ti][w] = vk[ti]; }
    }
    __syncthreads();
#pragma unroll
    for (int ti = 0; ti < 4; ti++) {
        const float varq = (rq[ti][0] + rq[ti][1] + rq[ti][2] + rq[ti][3]) * (1.f / HD);
        const float vark = (rk[ti][0] + rk[ti][1] + rk[ti][2] + rk[ti][3]) * (1.f / HD);
        sq[ti][hd] = yq[ti] * rsqrtf(varq + 1e-5f) * qnw[hd];
        sk[ti][hd] = yk[ti] * rsqrtf(vark + 1e-5f) * knw[hd];
    }
    __syncthreads();

    const float scale = 0.08838834764831845f * 1.4426950408889634f;

#pragma unroll
    for (int ti = 0; ti < 4; ti++) {
        const int t = t0 + ti;
        float oq, ok;
        if (hd < RD) {
            const float cs = cosb[t * RD + hd];
            const float sn = sinb[t * RD + hd];
            const float rqv = (hd < RD / 2) ? -sq[ti][hd + RD / 2] : sq[ti][hd - RD / 2];
            const float rkv = (hd < RD / 2) ? -sk[ti][hd + RD / 2] : sk[ti][hd - RD / 2];
            oq = -(sq[ti][hd] * cs + rqv * sn);
            ok = -(sk[ti][hd] * cs + rkv * sn);
        } else {
            oq = sq[ti][hd];
            ok = sk[ti][hd];
        }
        oq *= scale;

        const size_t o = ((size_t)h * T + t) * HD + hd;
        __nv_bfloat16 b;
        b = __float2bfloat16(oq);
        g_q2h[o] = b; g_q2l[o] = __float2bfloat16(oq - __bfloat162float(b));
        b = __float2bfloat16(ok);
        g_k2h[o] = b; g_k2l[o] = __float2bfloat16(ok - __bfloat162float(b));
        b = __float2bfloat16(yv[ti]);
        g_v2h[o] = b; g_v2l[o] = __float2bfloat16(yv[ti] - __bfloat162float(b));
    }
}

// ---------------- flash attention (best-known form) ---------------------------
#define FSTR   136
#define FQT    (64 * FSTR)
#define FKT    (32 * FSTR)
#define FSMEM  ((2 * FQT + 8 * FKT) * 2)  // 104448 B -> 2 CTAs/SM

__global__ __launch_bounds__(128, 2)
void flash_mma()
{
    extern __shared__ __nv_bfloat16 fsm[];

    const int tid  = threadIdx.x;
    const int lane = tid & 31;
    const int wm   = tid >> 5;
    const int h    = blockIdx.y;
    const int qt   = gridDim.x - 1 - blockIdx.x;
    const int q0   = qt * 64;

    const uint32_t sb = smem_u32(fsm);

    auto ldq = [&]() {
#pragma unroll
        for (int t = 0; t < 8; t++) {
            const int idx = t * 128 + tid;
            const int r   = idx >> 4;
            const int cc  = idx & 15;
            const uint32_t so = 2 * (r * FSTR + cc * 8);
            const size_t  go = ((size_t)h * T + q0 + r) * HD + cc * 8;
            CP16(sb + so,           g_q2h + go);
            CP16(sb + 2 * FQT + so, g_q2l + go);
        }
    };
    auto ldkv = [&](int kt2, int s) {
        const uint32_t kb = sb + 2 * (2 * FQT + (uint32_t)s * 4 * FKT);
#pragma unroll
        for (int t = 0; t < 4; t++) {
            const int idx = t * 128 + tid;
            const int r   = idx >> 4;
            const int cc  = idx & 15;
            const uint32_t so = 2 * (r * FSTR + cc * 8);
            const size_t  go = ((size_t)h * T + kt2 * 32 + r) * HD + cc * 8;
            CP16(kb + so,           g_k2h + go);
            CP16(kb + 2 * FKT + so, g_k2l + go);
            CP16(kb + 4 * FKT + so, g_v2h + go);
            CP16(kb + 6 * FKT + so, g_v2l + go);
        }
    };

    float acco[16][4];
#pragma unroll
    for (int nt = 0; nt < 16; nt++)
#pragma unroll
        for (int i = 0; i < 4; i++) acco[nt][i] = 0.f;
    float m0 = -1e30f, m1 = -1e30f, l0 = 0.f, l1 = 0.f;

    ldq(); ldkv(0, 0); CP_COMMIT();
    ldkv(1, 1); CP_COMMIT();

    const int r0l = wm * 16 + (lane >> 2);
    const int r1l = r0l + 8;
    const uint32_t qoff = 2 * ((wm * 16 + (lane & 15)) * FSTR + ((lane >> 4) << 3));
    const int krow = (lane & 7) + ((lane & 16) >> 1);
    const int rowMax = q0 + wm * 16 + 15;

    CP_WAIT(1);
    __syncthreads();
    uint32_t qh[8][4], ql[8][4];
#pragma unroll
    for (int j = 0; j < 8; j++) {
        const uint32_t qa = sb + qoff + 2 * (j * 16);
        LDSM4(qh[j][0], qh[j][1], qh[j][2], qh[j][3], qa);
        LDSM4(ql[j][0], ql[j][1], ql[j][2], ql[j][3], qa + 2 * FQT);
    }

    const int NKV = 2 * qt + 2;

    for (int kt = 0; kt < NKV; kt++) {
        if (kt > 0) {
            CP_WAIT(1);
            __syncthreads();
        }

        const bool active = (kt * 32 <= rowMax);
        const uint32_t kb = sb + 2 * (2 * FQT + (uint32_t)(kt & 1) * 4 * FKT);

        if (active) {
            float accA[4][4], accB[4][4];
#pragma unroll
            for (int nt = 0; nt < 4; nt++)
#pragma unroll
                for (int i = 0; i < 4; i++) { accA[nt][i] = 0.f; accB[nt][i] = 0.f; }

#pragma unroll
            for (int j = 0; j < 8; j++) {
                uint32_t bh[4][2], bl[4][2];
#pragma unroll
                for (int np = 0; np < 2; np++) {
                    const uint32_t ka = kb + 2 * ((np * 16 + krow) * FSTR + j * 16 + (lane & 8));
                    LDSM4(bh[2 * np][0], bh[2 * np][1], bh[2 * np + 1][0], bh[2 * np + 1][1], ka);
                    LDSM4(bl[2 * np][0], bl[2 * np][1], bl[2 * np + 1][0], bl[2 * np + 1][1],
                          ka + 2 * FKT);
                }
#pragma unroll
                for (int nt = 0; nt < 4; nt++) MMA16816(accA[nt], qh[j], bh[nt]);
#pragma unroll
                for (int nt = 0; nt < 4; nt++) MMA16816(accB[nt], qh[j], bl[nt]);
#pragma unroll
                for (int nt = 0; nt < 4; nt++) MMA16816(accB[nt], ql[j], bh[nt]);
            }

            float accs[4][4];
#pragma unroll
            for (int nt = 0; nt < 4; nt++)
#pragma unroll
                for (int i = 0; i < 4; i++) accs[nt][i] = accA[nt][i] + accB[nt][i];

            if (kt >= 2 * qt) {
                const int gr0 = q0 + r0l, gr1 = q0 + r1l;
#pragma unroll
                for (int nt = 0; nt < 4; nt++) {
                    const int c0 = kt * 32 + nt * 8 + 2 * (lane & 3);
                    if (c0     > gr0) accs[nt][0] = -1e30f;
                    if (c0 + 1 > gr0) accs[nt][1] = -1e30f;
                    if (c0     > gr1) accs[nt][2] = -1e30f;
                    if (c0 + 1 > gr1) accs[nt][3] = -1e30f;
                }
            }

            float mx0 = -1e30f, mx1 = -1e30f;
#pragma unroll
            for (int nt = 0; nt < 4; nt++) {
                mx0 = fmaxf(mx0, fmaxf(accs[nt][0], accs[nt][1]));
                mx1 = fmaxf(mx1, fmaxf(accs[nt][2], accs[nt][3]));
            }
            mx0 = fmaxf(mx0, __shfl_xor_sync(0xffffffffu, mx0, 1));
            mx0 = fmaxf(mx0, __shfl_xor_sync(0xffffffffu, mx0, 2));
            mx1 = fmaxf(mx1, __shfl_xor_sync(0xffffffffu, mx1, 1));
            mx1 = fmaxf(mx1, __shfl_xor_sync(0xffffffffu, mx1, 2));
            const float mn0 = fmaxf(m0, mx0), mn1 = fmaxf(m1, mx1);
            const float c0 = exp2f(m0 - mn0), c1 = exp2f(m1 - mn1);

            float p[4][4];
            float ps0 = 0.f, ps1 = 0.f;
#pragma unroll
            for (int nt = 0; nt < 4; nt++) {
                p[nt][0] = exp2f(accs[nt][0] - mn0); ps0 += p[nt][0];
                p[nt][1] = exp2f(accs[nt][1] - mn0); ps0 += p[nt][1];
                p[nt][2] = exp2f(accs[nt][2] - mn1); ps1 += p[nt][2];
                p[nt][3] = exp2f(accs[nt][3] - mn1); ps1 += p[nt][3];
            }
            ps0 += __shfl_xor_sync(0xffffffffu, ps0, 1);
            ps0 += __shfl_xor_sync(0xffffffffu, ps0, 2);
            ps1 += __shfl_xor_sync(0xffffffffu, ps1, 1);
            ps1 += __shfl_xor_sync(0xffffffffu, ps1, 2);
            l0 = l0 * c0 + ps0;
            l1 = l1 * c1 + ps1;
            m0 = mn0; m1 = mn1;

#pragma unroll
            for (int nt = 0; nt < 16; nt++) {
                acco[nt][0] *= c0; acco[nt][1] *= c0;
                acco[nt][2] *= c1; acco[nt][3] *= c1;
            }

            uint32_t pha[2][4], pla[2][4];
#pragma unroll
            for (int j = 0; j < 2; j++) {
                split2(p[2 * j][0],     p[2 * j][1],     pha[j][0], pla[j][0]);
                split2(p[2 * j][2],     p[2 * j][3],     pha[j][1], pla[j][1]);
                split2(p[2 * j + 1][0], p[2 * j + 1][1], pha[j][2], pla[j][2]);
                split2(p[2 * j + 1][2], p[2 * j + 1][3], pha[j][3], pla[j][3]);
            }

            const uint32_t vb = kb + 4 * FKT;
#pragma unroll
            for (int j = 0; j < 2; j++) {
                const int k0 = j * 16 + (lane & 15);
#pragma unroll
                for (int np = 0; np < 8; np++) {
                    const uint32_t va = vb + 2 * (k0 * FSTR + np * 16 + ((lane >> 4) << 3));
                    uint32_t vh[4], vl[4];
                    LDSM4T(vh[0], vh[1], vh[2], vh[3], va);
                    LDSM4T(vl[0], vl[1], vl[2], vl[3], va + 2 * FKT);
                    MMA16816(acco[2 * np],     pha[j], vh);
                    MMA16816(acco[2 * np + 1], pha[j], vh + 2);
                    MMA16816(acco[2 * np],     pha[j], vl);
                    MMA16816(acco[2 * np + 1], pha[j], vl + 2);
                    MMA16816(acco[2 * np],     pla[j], vh);
                    MMA16816(acco[2 * np + 1], pla[j], vh + 2);
                }
            }
        }

        __syncthreads();
        if (kt + 2 < NKV) ldkv(kt + 2, kt & 1);
        CP_COMMIT();
    }

    const float il0 = 1.f / l0, il1 = 1.f / l1;
#pragma unroll
    for (int nt = 0; nt < 16; nt++) {
        const int col = nt * 8 + 2 * (lane & 3);
        const float v0 = acco[nt][0] * il0;
        const float v1 = acco[nt][1] * il0;
        const float v2 = acco[nt][2] * il1;
        const float v3 = acco[nt][3] * il1;
        uint32_t hi, lo;
        const size_t o0 = (size_t)(q0 + r0l) * D + h * HD + col;
        const size_t o1 = (size_t)(q0 + r1l) * D + h * HD + col;
        split2(v0, v1, hi, lo);
        *(uint32_t*)&g_ah[o0] = hi; *(uint32_t*)&g_al[o0] = lo;
        split2(v2, v3, hi, lo);
        *(uint32_t*)&g_ah[o1] = hi; *(uint32_t*)&g_al[o1] = lo;
    }
}

// -----------------------------------------------------------------------------
extern "C" void kernel_launch(void* const* d_in, const int* in_sizes, int n_in,
                              void* d_out, int out_size)
{
    const float* x    = (const float*)d_in[0];
    const float* cosb = (const float*)d_in[1];
    const float* sinb = (const float*)d_in[2];
    const float* Wq   = (const float*)d_in[3];
    const float* Wk   = (const float*)d_in[4];
    const float* Wv   = (const float*)d_in[5];
    const float* Wo   = (const float*)d_in[6];
    const float* wq   = (const float*)d_in[7];
    const float* wk   = (const float*)d_in[8];
    const float* wv   = (const float*)d_in[9];
    const float* qnw  = (const float*)d_in[10];
    const float* knw  = (const float*)d_in[11];
    float* out = (float*)d_out;

    float *pq, *pk, *pv;
    __nv_bfloat16 *pxh, *pxl, *pwh, *pwl, *pah, *pal;
    cudaGetSymbolAddress((void**)&pq, g_q);
    cudaGetSymbolAddress((void**)&pk, g_k);
    cudaGetSymbolAddress((void**)&pv, g_v);
    cudaGetSymbolAddress((void**)&pxh, g_xh);
    cudaGetSymbolAddress((void**)&pxl, g_xl);
    cudaGetSymbolAddress((void**)&pwh, g_wh);
    cudaGetSymbolAddress((void**)&pwl, g_wl);
    cudaGetSymbolAddress((void**)&pah, g_ah);
    cudaGetSymbolAddress((void**)&pal, g_al);

    __nv_bfloat16* wh[4];
    __nv_bfloat16* wl[4];
    for (int i = 0; i < 4; i++) { wh[i] = pwh + (size_t)i * D * D; wl[i] = pwl + (size_t)i * D * D; }

    cudaFuncSetAttribute(gemm_bf16s, cudaFuncAttributeMaxDynamicSharedMemorySize, GEMM_SMEM);
    cudaFuncSetAttribute(flash_mma,  cudaFuncAttributeMaxDynamicSharedMemorySize, FSMEM);

    // 0) split x, Wq, Wk, Wv, Wo into bf16 hi/lo (wider grid for MLP)
    split_bf16<<<dim3(1024, 1, 5), 256>>>(x, pxh, pxl,
                                          Wq, wh[0], wl[0],
                                          Wk, wh[1], wl[1],
                                          Wv, wh[2], wl[2],
                                          Wo, wh[3], wl[3]);

    // 1) QKV projections (256x128 tiles)
    gemm_bf16s<<<dim3(D / 128, T / 256, 3), 256, GEMM_SMEM>>>(pxh, pxl,
                                                    wh[0], wl[0], wh[1], wl[1], wh[2], wl[2],
                                                    pq, pk, pv);

    // 2) conv + SiLU + RMSNorm + RoPE + transpose (4 t per block)
    fuse_post<<<dim3(T / 4, H), HD>>>(cosb, sinb, wq, wk, wv, qnw, knw);

    // 3) causal flash attention
    flash_mma<<<dim3(T / 64, H), 128, FSMEM>>>();

    // 4) O-proj -> d_out
    gemm_bf16s<<<dim3(D / 128, T / 256, 1), 256, GEMM_SMEM>>>(pah, pal,
                                                    wh[3], wl[3], wh[3], wl[3], wh[3], wl[3],
                                                    out, out, out);
}